// round 3
// baseline (speedup 1.0000x reference)
#include <cuda_runtime.h>
#include <math.h>

#define SEQ 2048
#define DMODEL 4096
#define NH 32
#define HD 128

// -------- scratch (static device globals; no allocations anywhere) --------
__device__ float g_qkv[(size_t)SEQ * 3 * DMODEL];          // 100.7 MB
__device__ float g_kt[(size_t)NH * HD * SEQ];              // 33.5 MB
__device__ float g_scores[(size_t)NH * SEQ * SEQ];         // 536.9 MB
__device__ float g_ctx[(size_t)SEQ * DMODEL];              // 33.5 MB
__device__ float g_cos[SEQ * (HD / 2)];
__device__ float g_sin[SEQ * (HD / 2)];

// ---------------------------------------------------------------------------
// Generic batched NN SGEMM: C[z] = alpha * A[z] (MxK) * B[z] (KxN)
// BM=BN=128, BK=8, 256 threads, 8x8 per-thread micro tile.
// Requires M%128==0, N%128==0, K%8==0, all ld divisible by 4 (float4 loads).
// ---------------------------------------------------------------------------
__global__ __launch_bounds__(256)
void sgemm_nn(const float* __restrict__ A, const float* __restrict__ B,
              float* __restrict__ C,
              int M, int N, int K, int lda, int ldb, int ldc,
              long long strideA, long long strideB, long long strideC,
              float alpha)
{
    const int BM = 128, BN = 128, BK = 8;
    __shared__ float As[BK][BM];
    __shared__ float Bs[BK][BN];

    A += (long long)blockIdx.z * strideA + (long long)blockIdx.y * BM * lda;
    B += (long long)blockIdx.z * strideB + (long long)blockIdx.x * BN;
    C += (long long)blockIdx.z * strideC + (long long)blockIdx.y * BM * ldc
         + (long long)blockIdx.x * BN;

    const int tid  = threadIdx.x;
    const int arow = tid >> 1;            // 0..127
    const int acol = (tid & 1) * 4;       // 0 or 4
    const int brow = tid >> 5;            // 0..7
    const int bcol = (tid & 31) * 4;      // 0..124

    const int tr = (tid / 16) * 8;        // 0..120
    const int tc = (tid % 16) * 8;        // 0..120

    float acc[8][8] = {};
    float ar[8], br[8];

    for (int k0 = 0; k0 < K; k0 += BK) {
        float4 av = *reinterpret_cast<const float4*>(A + (long long)arow * lda + k0 + acol);
        As[acol + 0][arow] = av.x;
        As[acol + 1][arow] = av.y;
        As[acol + 2][arow] = av.z;
        As[acol + 3][arow] = av.w;
        float4 bv = *reinterpret_cast<const float4*>(B + (long long)(k0 + brow) * ldb + bcol);
        *reinterpret_cast<float4*>(&Bs[brow][bcol]) = bv;
        __syncthreads();

        #pragma unroll
        for (int kk = 0; kk < BK; kk++) {
            #pragma unroll
            for (int i = 0; i < 8; i++) ar[i] = As[kk][tr + i];
            #pragma unroll
            for (int j = 0; j < 8; j++) br[j] = Bs[kk][tc + j];
            #pragma unroll
            for (int i = 0; i < 8; i++)
                #pragma unroll
                for (int j = 0; j < 8; j++)
                    acc[i][j] += ar[i] * br[j];
        }
        __syncthreads();
    }

    #pragma unroll
    for (int i = 0; i < 8; i++) {
        #pragma unroll
        for (int j = 0; j < 8; j += 4) {
            float4 v;
            v.x = acc[i][j + 0] * alpha;
            v.y = acc[i][j + 1] * alpha;
            v.z = acc[i][j + 2] * alpha;
            v.w = acc[i][j + 3] * alpha;
            *reinterpret_cast<float4*>(C + (long long)(tr + i) * ldc + tc + j) = v;
        }
    }
}

// ---------------------------------------------------------------------------
// RoPE cos/sin table: one entry per (s, i), i in [0, 64).
// Mimics the reference's fp32 rounding: freq rounded to fp32, angle = fp32
// product, trig evaluated accurately (double) on that fp32 angle.
// ---------------------------------------------------------------------------
__global__ void build_rope_table()
{
    int idx = blockIdx.x * blockDim.x + threadIdx.x;
    if (idx >= SEQ * (HD / 2)) return;
    int i = idx % (HD / 2);
    int s = idx / (HD / 2);
    double freq_d = pow(10000.0, -(double)(2 * i) / (double)HD);
    float freq   = (float)freq_d;
    float angle  = (float)s * freq;            // fp32 product like jnp.outer
    g_cos[idx] = (float)cos((double)angle);
    g_sin[idx] = (float)sin((double)angle);
}

// In-place RoPE on the q and k slices of the qkv buffer.
__global__ __launch_bounds__(256)
void rope_kernel(float* __restrict__ qkv)
{
    int idx = blockIdx.x * blockDim.x + threadIdx.x;      // (s, h, i)
    if (idx >= SEQ * NH * (HD / 2)) return;
    int i = idx % (HD / 2);
    int h = (idx / (HD / 2)) % NH;
    int s = idx / ((HD / 2) * NH);

    float c  = g_cos[s * (HD / 2) + i];
    float sn = g_sin[s * (HD / 2) + i];

    float* q = qkv + (long long)s * (3 * DMODEL) + h * HD + 2 * i;
    float* k = q + DMODEL;

    float q0 = q[0], q1 = q[1];
    q[0] = q0 * c - q1 * sn;
    q[1] = q0 * sn + q1 * c;
    float k0 = k[0], k1 = k[1];
    k[0] = k0 * c - k1 * sn;
    k[1] = k0 * sn + k1 * c;
}

// ---------------------------------------------------------------------------
// Transpose K into [h][d][s] so the score GEMM is NN with coalesced B loads.
// ---------------------------------------------------------------------------
__global__ void transpose_k(const float* __restrict__ qkv, float* __restrict__ kt)
{
    __shared__ float tile[32][33];
    int h  = blockIdx.z;
    int d0 = blockIdx.x * 32;
    int s0 = blockIdx.y * 32;
    int x = threadIdx.x, y = threadIdx.y;    // 32 x 8

    #pragma unroll
    for (int r = 0; r < 32; r += 8)
        tile[y + r][x] = qkv[(long long)(s0 + y + r) * (3 * DMODEL) + DMODEL + h * HD + d0 + x];
    __syncthreads();
    #pragma unroll
    for (int r = 0; r < 32; r += 8)
        kt[(long long)h * HD * SEQ + (long long)(d0 + y + r) * SEQ + s0 + x] = tile[x][y + r];
}

// ---------------------------------------------------------------------------
// Row softmax over the 2048-wide score rows. One block (256 threads) per row.
// ---------------------------------------------------------------------------
__global__ __launch_bounds__(256)
void softmax_rows(float* __restrict__ scores)
{
    long long row = blockIdx.x;
    float* p = scores + row * (long long)SEQ;
    int t = threadIdx.x;

    float v[8];
    float m = -1e30f;
    #pragma unroll
    for (int j = 0; j < 8; j++) { v[j] = p[t + 256 * j]; m = fmaxf(m, v[j]); }
    #pragma unroll
    for (int o = 16; o > 0; o >>= 1) m = fmaxf(m, __shfl_xor_sync(0xffffffffu, m, o));

    __shared__ float red[8];
    if ((t & 31) == 0) red[t >> 5] = m;
    __syncthreads();
    float bm = red[0];
    #pragma unroll
    for (int i = 1; i < 8; i++) bm = fmaxf(bm, red[i]);

    float s = 0.f;
    #pragma unroll
    for (int j = 0; j < 8; j++) { v[j] = expf(v[j] - bm); s += v[j]; }
    #pragma unroll
    for (int o = 16; o > 0; o >>= 1) s += __shfl_xor_sync(0xffffffffu, s, o);
    __syncthreads();
    if ((t & 31) == 0) red[t >> 5] = s;
    __syncthreads();
    float bs = 0.f;
    #pragma unroll
    for (int i = 0; i < 8; i++) bs += red[i];
    float inv = 1.0f / bs;
    #pragma unroll
    for (int j = 0; j < 8; j++) p[t + 256 * j] = v[j] * inv;
}

// ---------------------------------------------------------------------------
extern "C" void kernel_launch(void* const* d_in, const int* in_sizes, int n_in,
                              void* d_out, int out_size)
{
    const float* hidden = (const float*)d_in[0];   // [2048, 4096]
    const float* wqkv   = (const float*)d_in[1];   // [4096, 12288]
    const float* wo     = (const float*)d_in[2];   // [4096, 4096]
    float* out = (float*)d_out;                    // [2048, 4096]

    float *qkv, *kt, *scores, *ctx;
    cudaGetSymbolAddress((void**)&qkv,    g_qkv);
    cudaGetSymbolAddress((void**)&kt,     g_kt);
    cudaGetSymbolAddress((void**)&scores, g_scores);
    cudaGetSymbolAddress((void**)&ctx,    g_ctx);

    // 1) qkv = hidden @ Wqkv  [2048 x 12288]
    sgemm_nn<<<dim3(12288 / 128, 2048 / 128, 1), 256>>>(
        hidden, wqkv, qkv,
        2048, 12288, 4096, 4096, 12288, 12288,
        0, 0, 0, 1.0f);

    // 2) RoPE
    build_rope_table<<<(SEQ * (HD / 2) + 255) / 256, 256>>>();
    rope_kernel<<<(SEQ * NH * (HD / 2) + 255) / 256, 256>>>(qkv);

    // 3) K transpose -> [h][d][s]
    transpose_k<<<dim3(HD / 32, SEQ / 32, NH), dim3(32, 8)>>>(qkv, kt);

    // 4) scores[h] = (1/sqrt(HD)) * Q[h] @ Kt[h]   [2048 x 2048] x 32
    sgemm_nn<<<dim3(2048 / 128, 2048 / 128, NH), 256>>>(
        qkv /* q at col 0 */, kt, scores,
        2048, 2048, 128, 3 * DMODEL, SEQ, SEQ,
        /*strideA=*/HD, /*strideB=*/(long long)HD * SEQ, /*strideC=*/(long long)SEQ * SEQ,
        0.08838834764831845f);

    // 5) softmax rows
    softmax_rows<<<NH * SEQ, 256>>>(scores);

    // 6) ctx[h] = P[h] @ V[h]   [2048 x 128] x 32, written to [s, h*128+d]
    sgemm_nn<<<dim3(128 / 128, 2048 / 128, NH), 256>>>(
        scores, qkv + 2 * DMODEL /* v */, ctx,
        2048, 128, 2048, SEQ, 3 * DMODEL, DMODEL,
        /*strideA=*/(long long)SEQ * SEQ, /*strideB=*/HD, /*strideC=*/HD,
        1.0f);

    // 7) out = ctx @ Wo  [2048 x 4096]
    sgemm_nn<<<dim3(4096 / 128, 2048 / 128, 1), 256>>>(
        ctx, wo, out,
        2048, 4096, 4096, 4096, 4096, 4096,
        0, 0, 0, 1.0f);
}

// round 5
// speedup vs baseline: 2.7211x; 2.7211x over previous
#include <cuda_runtime.h>
#include <cuda_bf16.h>
#include <math.h>
#include <stdint.h>

#define SEQ 2048
#define DMODEL 4096
#define NH 32
#define HD 128

// ===========================================================================
// PTX helpers (sm_103-safe subset: NO tcgen05 / NO 'a'-only features)
// ===========================================================================
__device__ __forceinline__ uint32_t smem_u32(const void* p) {
    uint32_t a;
    asm("{ .reg .u64 t; cvta.to.shared.u64 t, %1; cvt.u32.u64 %0, t; }" : "=r"(a) : "l"(p));
    return a;
}
#define MBARRIER_INIT(addr, cnt) \
    asm volatile("mbarrier.init.shared.b64 [%0], %1;" :: "r"((uint32_t)(addr)), "r"((uint32_t)(cnt)) : "memory")
#define MBARRIER_EXPECT_TX(addr, bytes) \
    asm volatile("mbarrier.arrive.expect_tx.shared.b64 _, [%0], %1;" :: "r"((uint32_t)(addr)), "r"((uint32_t)(bytes)) : "memory")
#define MBARRIER_ARRIVE(addr) \
    asm volatile("mbarrier.arrive.shared.b64 _, [%0];" :: "r"((uint32_t)(addr)) : "memory")

#define MBARRIER_WAIT_PARITY(mbar_smem_addr, phase_parity) do { \
    uint32_t _mbar = (uint32_t)(mbar_smem_addr); \
    uint32_t _parity = (uint32_t)(phase_parity); \
    uint32_t _done; \
    asm volatile("{\n\t.reg .pred p;\n\t" \
        "mbarrier.try_wait.parity.acquire.cta.shared::cta.b64 p, [%1], %2;\n\t" \
        "selp.b32 %0, 1, 0, p;\n\t}" : "=r"(_done) : "r"(_mbar), "r"(_parity) : "memory"); \
    if (!_done) { \
        asm volatile("{\n\t.reg .pred P1;\n\t" \
            "WAIT_LOOP_%=:\n\t" \
            "mbarrier.try_wait.parity.acquire.cta.shared::cta.b64 P1, [%0], %1, 0x989680;\n\t" \
            "@P1 bra.uni WAIT_DONE_%=;\n\t" \
            "bra.uni WAIT_LOOP_%=;\n\t" \
            "WAIT_DONE_%=:\n\t}" :: "r"(_mbar), "r"(_parity) : "memory"); \
    } \
} while(0)

#define MBARRIER_WAIT_PARITY_RELAXED(mbar_smem_addr, phase_parity) do { \
    uint32_t _mbar = (uint32_t)(mbar_smem_addr); \
    uint32_t _parity = (uint32_t)(phase_parity); \
    uint32_t _done; \
    asm volatile("{\n\t.reg .pred p;\n\t" \
        "mbarrier.try_wait.parity.relaxed.cta.shared::cta.b64 p, [%1], %2, 0x989680;\n\t" \
        "selp.b32 %0, 1, 0, p;\n\t}" : "=r"(_done) : "r"(_mbar), "r"(_parity) : "memory"); \
    if (!_done) { \
        asm volatile("{\n\t.reg .pred P1;\n\t" \
            "WAIT_LOOP_%=:\n\t" \
            "mbarrier.try_wait.parity.relaxed.cta.shared::cta.b64 P1, [%0], %1, 0x989680;\n\t" \
            "@P1 bra.uni WAIT_DONE_%=;\n\t" \
            "bra.uni WAIT_LOOP_%=;\n\t" \
            "WAIT_DONE_%=:\n\t}" :: "r"(_mbar), "r"(_parity) : "memory"); \
    } \
} while(0)

// plain bulk copy gmem -> smem with mbarrier complete_tx (sm_90 baseline)
__device__ __forceinline__ void bulk_g2s(uint32_t dst, const void* src,
                                         uint32_t bytes, uint32_t mbar) {
    asm volatile(
        "cp.async.bulk.shared::cluster.global.mbarrier::complete_tx::bytes [%0], [%1], %2, [%3];"
        :: "r"(dst), "l"(src), "r"(bytes), "r"(mbar) : "memory");
}

__device__ __forceinline__ void ldsm_x4(uint32_t addr, uint32_t& r0, uint32_t& r1,
                                        uint32_t& r2, uint32_t& r3) {
    asm volatile("ldmatrix.sync.aligned.m8n8.x4.shared.b16 {%0,%1,%2,%3}, [%4];"
        : "=r"(r0), "=r"(r1), "=r"(r2), "=r"(r3) : "r"(addr));
}

__device__ __forceinline__ void mma_bf16(float* c, uint32_t a0, uint32_t a1,
                                         uint32_t a2, uint32_t a3,
                                         uint32_t b0, uint32_t b1) {
    asm volatile(
        "mma.sync.aligned.m16n8k16.row.col.f32.bf16.bf16.f32 "
        "{%0,%1,%2,%3}, {%4,%5,%6,%7}, {%8,%9}, {%0,%1,%2,%3};"
        : "+f"(c[0]), "+f"(c[1]), "+f"(c[2]), "+f"(c[3])
        : "r"(a0), "r"(a1), "r"(a2), "r"(a3), "r"(b0), "r"(b1));
}

// ===========================================================================
// Scratch (static device globals; no allocations anywhere)
// ===========================================================================
__device__ float g_qkv[(size_t)SEQ * 3 * DMODEL];
__device__ float g_scores[(size_t)NH * SEQ * SEQ];
__device__ float g_ctx[(size_t)SEQ * DMODEL];
__device__ __align__(128) __nv_bfloat16 g_x2[(size_t)SEQ * 3 * DMODEL];
__device__ __align__(128) __nv_bfloat16 g_w1[(size_t)3 * DMODEL * 3 * DMODEL];
__device__ __align__(128) __nv_bfloat16 g_w2[(size_t)DMODEL * 3 * DMODEL];
__device__ __align__(128) __nv_bfloat16 g_q2[(size_t)NH * SEQ * 3 * HD];
__device__ __align__(128) __nv_bfloat16 g_k2[(size_t)NH * SEQ * 3 * HD];
__device__ __align__(128) __nv_bfloat16 g_vt[(size_t)NH * HD * 3 * SEQ];
__device__ __align__(128) __nv_bfloat16 g_p2[(size_t)NH * SEQ * 3 * SEQ];
__device__ __align__(128) __nv_bfloat16 g_c2[(size_t)SEQ * 3 * DMODEL];
__device__ float g_cos[SEQ * (HD / 2)];
__device__ float g_sin[SEQ * (HD / 2)];

// ===========================================================================
// Tiled/swizzled gmem layout: 128x64-bf16 tiles (16KB, SW128-swizzled),
// tile (rt, kt) at ((rt*ktiles + kt) << 14) bytes.
// ===========================================================================
__device__ __forceinline__ size_t tile_off(int r, int k, int ktiles) {
    int rt = r >> 7, kt = k >> 6;
    uint32_t b = (uint32_t)((r & 127) * 128 + (k & 63) * 2);
    b ^= ((b >> 3) & 0x70u);
    return ((size_t)(rt * ktiles + kt) << 14) + b;
}

// hi/lo split pair at (r, k..k+1). A-side: [hi | lo | hi]; B-side: [hi | hi | lo]
__device__ __forceinline__ void write_split_pair(__nv_bfloat16* out, int r, int k,
                                                 int K, int kt3, float a, float b,
                                                 int bside) {
    __nv_bfloat16 ha = __float2bfloat16(a), hb = __float2bfloat16(b);
    __nv_bfloat16 la = __float2bfloat16(a - __bfloat162float(ha));
    __nv_bfloat16 lb = __float2bfloat16(b - __bfloat162float(hb));
    __nv_bfloat162 hi; hi.x = ha; hi.y = hb;
    __nv_bfloat162 lo; lo.x = la; lo.y = lb;
    char* o = (char*)out;
    *(__nv_bfloat162*)(o + tile_off(r, k, kt3)) = hi;
    if (bside) {
        *(__nv_bfloat162*)(o + tile_off(r, K + k, kt3))     = hi;
        *(__nv_bfloat162*)(o + tile_off(r, 2 * K + k, kt3)) = lo;
    } else {
        *(__nv_bfloat162*)(o + tile_off(r, K + k, kt3))     = lo;
        *(__nv_bfloat162*)(o + tile_off(r, 2 * K + k, kt3)) = hi;
    }
}

__global__ __launch_bounds__(256)
void split_tiles(const float* __restrict__ in, __nv_bfloat16* __restrict__ out,
                 int R, int K, int ldin, long long izs, long long ozs, int bside)
{
    int z = blockIdx.y;
    long long idx = (long long)blockIdx.x * 256 + threadIdx.x;
    long long tot = (long long)R * (K / 2);
    if (idx >= tot) return;
    int r = (int)(idx / (K / 2));
    int k = (int)(idx - (long long)r * (K / 2)) * 2;
    const float* p = in + (long long)z * izs + (long long)r * ldin + k;
    float a = p[0], b = p[1];
    write_split_pair(out + (long long)z * ozs, r, k, K, (3 * K) / 64, a, b, bside);
}

__global__ __launch_bounds__(256)
void transpose_split_tiles(const float* __restrict__ in, __nv_bfloat16* __restrict__ out,
                           int K, int N, int ldin, long long izs, long long ozs, int bside)
{
    __shared__ float t[32][33];
    int z = blockIdx.z;
    const float* inz = in + (long long)z * izs;
    __nv_bfloat16* outz = out + (long long)z * ozs;
    int n0 = blockIdx.x * 32, k0 = blockIdx.y * 32;
    int x = threadIdx.x, y = threadIdx.y;   // 32 x 8
    #pragma unroll
    for (int r = 0; r < 32; r += 8)
        t[y + r][x] = inz[(long long)(k0 + y + r) * ldin + n0 + x];
    __syncthreads();
    int kt3 = (3 * K) / 64;
    int n = n0 + x;
    #pragma unroll
    for (int p = 0; p < 2; p++) {
        int kk = y * 4 + p * 2;
        float a = t[kk][x], b = t[kk + 1][x];
        write_split_pair(outz, n, k0 + kk, K, kt3, a, b, bside);
    }
}

// ===========================================================================
// mma.sync bf16 GEMM: C[z](M x N) = alpha * A'[z] @ B'[z]^T, K' = nk*64
// BM=256, BN=128, BK=64. 256 threads (8 warps, 4x2), warp tile 64x64.
// Pipeline: 3 stages x 48KB (A0,A1,B tiles), single-thread bulk-copy producer.
// ===========================================================================
#define GST 3
#define STAGE_BYTES 49152
#define GEMM_DYN_SMEM (GST * STAGE_BYTES + 1024)

__global__ __launch_bounds__(256, 1)
void gemm_mma(const __nv_bfloat16* __restrict__ A, const __nv_bfloat16* __restrict__ B,
              float* __restrict__ C, int nk, int ldc,
              long long Az, long long Bz, long long Cz, float alpha)
{
    extern __shared__ char dyn[];
    __shared__ __align__(8) unsigned long long s_mbar[2 * GST];  // full[3], empty[3]

    const int tid  = threadIdx.x;
    const int wid  = tid >> 5;
    const int lane = tid & 31;
    const int wm = wid >> 1, wn = wid & 1;
    const int mt2 = blockIdx.x, ntb = blockIdx.y, z = blockIdx.z;

    uint32_t stages = (smem_u32(dyn) + 1023u) & ~1023u;
    uint32_t mb = smem_u32(s_mbar);

    if (tid == 0) {
        #pragma unroll
        for (int i = 0; i < GST; i++)  MBARRIER_INIT(mb + i * 8, 1);
        #pragma unroll
        for (int i = GST; i < 2 * GST; i++) MBARRIER_INIT(mb + i * 8, 8);
    }
    __syncthreads();

    const char* Ab = (const char*)A + (size_t)z * Az * 2 + (((size_t)(2 * mt2) * nk) << 14);
    const char* Bb = (const char*)B + (size_t)z * Bz * 2 + (((size_t)ntb * nk) << 14);
    const size_t Astride = ((size_t)nk << 14);   // between the two 128-row A tiles

    // producer prologue: stages for chunks 0 .. GST-2
    if (tid == 0) {
        for (int c = 0; c < GST - 1 && c < nk; c++) {
            uint32_t st = stages + c * STAGE_BYTES;
            MBARRIER_EXPECT_TX(mb + c * 8, STAGE_BYTES);
            bulk_g2s(st,         Ab + ((size_t)c << 14),           16384, mb + c * 8);
            bulk_g2s(st + 16384, Ab + Astride + ((size_t)c << 14), 16384, mb + c * 8);
            bulk_g2s(st + 32768, Bb + ((size_t)c << 14),           16384, mb + c * 8);
        }
    }

    // per-lane ldmatrix addressing (SW128: addr = rowbase + ((row&7)<<4 ^ colb))
    const int r_a = wm * 64 + (lane & 15);
    const uint32_t a_rowoff = ((uint32_t)(r_a >> 7) << 14) + (uint32_t)(r_a & 127) * 128;
    const uint32_t a_sw = (uint32_t)(r_a & 7) << 4;
    const uint32_t cbA  = (uint32_t)(lane >> 4) * 16;

    const int r_b = wn * 64 + (lane & 7) + ((lane >> 4) & 1) * 8;
    const uint32_t b_rowoff = 32768u + (uint32_t)r_b * 128;
    const uint32_t b_sw = (uint32_t)(r_b & 7) << 4;
    const uint32_t cbB  = (uint32_t)((lane >> 3) & 1) * 16;

    float acc[4][8][4];
    #pragma unroll
    for (int i = 0; i < 4; i++)
        #pragma unroll
        for (int j = 0; j < 8; j++)
            #pragma unroll
            for (int q = 0; q < 4; q++) acc[i][j][q] = 0.f;

    for (int c = 0; c < nk; c++) {
        // producer: issue chunk c + GST-1
        if (tid == 0) {
            int j = c + GST - 1;
            if (j < nk) {
                int s2 = j % GST;
                if (j >= GST)
                    MBARRIER_WAIT_PARITY_RELAXED(mb + (GST + s2) * 8, ((j / GST) - 1) & 1);
                uint32_t st = stages + s2 * STAGE_BYTES;
                MBARRIER_EXPECT_TX(mb + s2 * 8, STAGE_BYTES);
                bulk_g2s(st,         Ab + ((size_t)j << 14),           16384, mb + s2 * 8);
                bulk_g2s(st + 16384, Ab + Astride + ((size_t)j << 14), 16384, mb + s2 * 8);
                bulk_g2s(st + 32768, Bb + ((size_t)j << 14),           16384, mb + s2 * 8);
            }
        }

        int s = c % GST;
        MBARRIER_WAIT_PARITY(mb + s * 8, (c / GST) & 1);
        uint32_t st = stages + s * STAGE_BYTES;
        uint32_t abase = st + a_rowoff;
        uint32_t bbase = st + b_rowoff;

        #pragma unroll
        for (int kk = 0; kk < 4; kk++) {
            uint32_t a[4][4];
            uint32_t acol = a_sw ^ (cbA + kk * 32);
            #pragma unroll
            for (int mt = 0; mt < 4; mt++)
                ldsm_x4(abase + mt * 2048 + acol, a[mt][0], a[mt][1], a[mt][2], a[mt][3]);

            uint32_t b[8][2];
            uint32_t bcol = b_sw ^ (cbB + kk * 32);
            #pragma unroll
            for (int u = 0; u < 4; u++) {
                uint32_t r0, r1, r2, r3;
                ldsm_x4(bbase + u * 2048 + bcol, r0, r1, r2, r3);
                b[2 * u][0] = r0; b[2 * u][1] = r1;
                b[2 * u + 1][0] = r2; b[2 * u + 1][1] = r3;
            }

            #pragma unroll
            for (int mt = 0; mt < 4; mt++)
                #pragma unroll
                for (int nt = 0; nt < 8; nt++)
                    mma_bf16(acc[mt][nt], a[mt][0], a[mt][1], a[mt][2], a[mt][3],
                             b[nt][0], b[nt][1]);
        }

        if (lane == 0) MBARRIER_ARRIVE(mb + (GST + s) * 8);
    }

    // epilogue
    float* Cb = C + (size_t)z * Cz;
    const int row0 = mt2 * 256 + wm * 64;
    const int col0 = ntb * 128 + wn * 64;
    #pragma unroll
    for (int mt = 0; mt < 4; mt++) {
        int r = row0 + mt * 16 + (lane >> 2);
        #pragma unroll
        for (int nt = 0; nt < 8; nt++) {
            int cc = col0 + nt * 8 + (lane & 3) * 2;
            float2 v0 = { acc[mt][nt][0] * alpha, acc[mt][nt][1] * alpha };
            float2 v1 = { acc[mt][nt][2] * alpha, acc[mt][nt][3] * alpha };
            *(float2*)(Cb + (size_t)r * ldc + cc)       = v0;
            *(float2*)(Cb + (size_t)(r + 8) * ldc + cc) = v1;
        }
    }
}

// ===========================================================================
// RoPE
// ===========================================================================
__global__ void build_rope_table()
{
    int idx = blockIdx.x * blockDim.x + threadIdx.x;
    if (idx >= SEQ * (HD / 2)) return;
    int i = idx % (HD / 2);
    int s = idx / (HD / 2);
    double freq_d = pow(10000.0, -(double)(2 * i) / (double)HD);
    float freq  = (float)freq_d;
    float angle = (float)s * freq;
    g_cos[idx] = (float)cos((double)angle);
    g_sin[idx] = (float)sin((double)angle);
}

__global__ __launch_bounds__(256)
void rope_kernel(float* __restrict__ qkv)
{
    int idx = blockIdx.x * blockDim.x + threadIdx.x;
    if (idx >= SEQ * NH * (HD / 2)) return;
    int i = idx % (HD / 2);
    int h = (idx / (HD / 2)) % NH;
    int s = idx / ((HD / 2) * NH);

    float c  = g_cos[s * (HD / 2) + i];
    float sn = g_sin[s * (HD / 2) + i];

    float* q = qkv + (long long)s * (3 * DMODEL) + h * HD + 2 * i;
    float* k = q + DMODEL;

    float q0 = q[0], q1 = q[1];
    q[0] = q0 * c - q1 * sn;
    q[1] = q0 * sn + q1 * c;
    float k0 = k[0], k1 = k[1];
    k[0] = k0 * c - k1 * sn;
    k[1] = k0 * sn + k1 * c;
}

// ===========================================================================
// Softmax rows -> P tiled split layout (A-side, K=2048)
// ===========================================================================
__global__ __launch_bounds__(256)
void softmax_p(const float* __restrict__ scores, __nv_bfloat16* __restrict__ P)
{
    long long row = blockIdx.x;
    int h = (int)(row >> 11);
    int r = (int)(row & 2047);
    const float* p = scores + row * (long long)SEQ;
    int t = threadIdx.x;

    float v[8];
    const float4* p4 = (const float4*)(p + t * 8);
    float4 va = p4[0], vb = p4[1];
    v[0] = va.x; v[1] = va.y; v[2] = va.z; v[3] = va.w;
    v[4] = vb.x; v[5] = vb.y; v[6] = vb.z; v[7] = vb.w;

    float m = -1e30f;
    #pragma unroll
    for (int j = 0; j < 8; j++) m = fmaxf(m, v[j]);
    #pragma unroll
    for (int o = 16; o > 0; o >>= 1) m = fmaxf(m, __shfl_xor_sync(0xffffffffu, m, o));

    __shared__ float red[8];
    if ((t & 31) == 0) red[t >> 5] = m;
    __syncthreads();
    float bm = red[0];
    #pragma unroll
    for (int i = 1; i < 8; i++) bm = fmaxf(bm, red[i]);

    float s = 0.f;
    #pragma unroll
    for (int j = 0; j < 8; j++) { v[j] = expf(v[j] - bm); s += v[j]; }
    #pragma unroll
    for (int o = 16; o > 0; o >>= 1) s += __shfl_xor_sync(0xffffffffu, s, o);
    __syncthreads();
    if ((t & 31) == 0) red[t >> 5] = s;
    __syncthreads();
    float bs = 0.f;
    #pragma unroll
    for (int i = 0; i < 8; i++) bs += red[i];
    float inv = 1.0f / bs;

    __nv_bfloat16* Pb = P + (long long)h * SEQ * (3 * SEQ);
    #pragma unroll
    for (int jj = 0; jj < 4; jj++) {
        int k = t * 8 + jj * 2;
        write_split_pair(Pb, r, k, SEQ, (3 * SEQ) / 64,
                         v[jj * 2] * inv, v[jj * 2 + 1] * inv, /*bside=*/0);
    }
}

// ===========================================================================
extern "C" void kernel_launch(void* const* d_in, const int* in_sizes, int n_in,
                              void* d_out, int out_size)
{
    const float* hidden = (const float*)d_in[0];   // [2048, 4096]
    const float* wqkv   = (const float*)d_in[1];   // [4096, 12288]
    const float* wo     = (const float*)d_in[2];   // [4096, 4096]
    float* out = (float*)d_out;                    // [2048, 4096]

    float *qkv, *scores, *ctx;
    __nv_bfloat16 *x2, *w1, *w2, *q2, *k2, *vt, *p2, *c2;
    cudaGetSymbolAddress((void**)&qkv,    g_qkv);
    cudaGetSymbolAddress((void**)&scores, g_scores);
    cudaGetSymbolAddress((void**)&ctx,    g_ctx);
    cudaGetSymbolAddress((void**)&x2, g_x2);
    cudaGetSymbolAddress((void**)&w1, g_w1);
    cudaGetSymbolAddress((void**)&w2, g_w2);
    cudaGetSymbolAddress((void**)&q2, g_q2);
    cudaGetSymbolAddress((void**)&k2, g_k2);
    cudaGetSymbolAddress((void**)&vt, g_vt);
    cudaGetSymbolAddress((void**)&p2, g_p2);
    cudaGetSymbolAddress((void**)&c2, g_c2);

    cudaFuncSetAttribute(gemm_mma, cudaFuncAttributeMaxDynamicSharedMemorySize, GEMM_DYN_SMEM);

    // ---- operand conversion (split + pre-swizzle into tiled layout) ----
    split_tiles<<<dim3((2048 * 2048 + 255) / 256, 1), 256>>>(
        hidden, x2, 2048, 4096, 4096, 0, 0, /*bside=*/0);
    transpose_split_tiles<<<dim3(12288 / 32, 4096 / 32, 1), dim3(32, 8)>>>(
        wqkv, w1, 4096, 12288, 12288, 0, 0, /*bside=*/1);
    transpose_split_tiles<<<dim3(4096 / 32, 4096 / 32, 1), dim3(32, 8)>>>(
        wo, w2, 4096, 4096, 4096, 0, 0, /*bside=*/1);

    // ---- QKV GEMM: [2048, 12288] = X' @ Wqkv'^T  (nk = 192) ----
    gemm_mma<<<dim3(8, 96, 1), 256, GEMM_DYN_SMEM>>>(
        x2, w1, qkv, 192, 12288, 0, 0, 0, 1.0f);

    // ---- RoPE ----
    build_rope_table<<<(SEQ * (HD / 2) + 255) / 256, 256>>>();
    rope_kernel<<<(SEQ * NH * (HD / 2) + 255) / 256, 256>>>(qkv);

    // ---- per-head operand prep ----
    split_tiles<<<dim3((2048 * 64 + 255) / 256, NH), 256>>>(
        qkv, q2, 2048, 128, 3 * DMODEL, /*izs=*/HD, /*ozs=*/(long long)SEQ * 3 * HD, 0);
    split_tiles<<<dim3((2048 * 64 + 255) / 256, NH), 256>>>(
        qkv + DMODEL, k2, 2048, 128, 3 * DMODEL, HD, (long long)SEQ * 3 * HD, 1);
    transpose_split_tiles<<<dim3(128 / 32, 2048 / 32, NH), dim3(32, 8)>>>(
        qkv + 2 * DMODEL, vt, 2048, 128, 3 * DMODEL, HD, (long long)HD * 3 * SEQ, 1);

    // ---- scores[h] = (1/sqrt(HD)) * Q'[h] @ K'[h]^T  (nk = 6) ----
    gemm_mma<<<dim3(8, 16, NH), 256, GEMM_DYN_SMEM>>>(
        q2, k2, scores, 6, SEQ,
        (long long)SEQ * 3 * HD, (long long)SEQ * 3 * HD, (long long)SEQ * SEQ,
        0.08838834764831845f);

    // ---- softmax -> P' tiled split ----
    softmax_p<<<NH * SEQ, 256>>>(scores, p2);

    // ---- ctx[h] = P'[h] @ V'[h]^T  (nk = 96, N = 128) ----
    gemm_mma<<<dim3(8, 1, NH), 256, GEMM_DYN_SMEM>>>(
        p2, vt, ctx, 96, DMODEL,
        (long long)SEQ * 3 * SEQ, (long long)HD * 3 * SEQ, /*Cz=*/HD,
        1.0f);

    // ---- ctx split (A-side) ----
    split_tiles<<<dim3((2048 * 2048 + 255) / 256, 1), 256>>>(
        ctx, c2, 2048, 4096, 4096, 0, 0, 0);

    // ---- out = ctx' @ Wo'^T  (nk = 192) ----
    gemm_mma<<<dim3(8, 32, 1), 256, GEMM_DYN_SMEM>>>(
        c2, w2, out, 192, 4096, 0, 0, 0, 1.0f);
}

// round 6
// speedup vs baseline: 3.5372x; 1.2999x over previous
#include <cuda_runtime.h>
#include <cuda_bf16.h>
#include <math.h>
#include <stdint.h>

#define SEQ 2048
#define DMODEL 4096
#define NH 32
#define HD 128

// ===========================================================================
// PTX helpers (sm_103-safe subset: NO tcgen05 / NO 'a'-only features)
// ===========================================================================
__device__ __forceinline__ uint32_t smem_u32(const void* p) {
    uint32_t a;
    asm("{ .reg .u64 t; cvta.to.shared.u64 t, %1; cvt.u32.u64 %0, t; }" : "=r"(a) : "l"(p));
    return a;
}
#define MBARRIER_INIT(addr, cnt) \
    asm volatile("mbarrier.init.shared.b64 [%0], %1;" :: "r"((uint32_t)(addr)), "r"((uint32_t)(cnt)) : "memory")
#define MBARRIER_EXPECT_TX(addr, bytes) \
    asm volatile("mbarrier.arrive.expect_tx.shared.b64 _, [%0], %1;" :: "r"((uint32_t)(addr)), "r"((uint32_t)(bytes)) : "memory")
#define MBARRIER_ARRIVE(addr) \
    asm volatile("mbarrier.arrive.shared.b64 _, [%0];" :: "r"((uint32_t)(addr)) : "memory")

#define MBARRIER_WAIT_PARITY(mbar_smem_addr, phase_parity) do { \
    uint32_t _mbar = (uint32_t)(mbar_smem_addr); \
    uint32_t _parity = (uint32_t)(phase_parity); \
    uint32_t _done; \
    asm volatile("{\n\t.reg .pred p;\n\t" \
        "mbarrier.try_wait.parity.acquire.cta.shared::cta.b64 p, [%1], %2;\n\t" \
        "selp.b32 %0, 1, 0, p;\n\t}" : "=r"(_done) : "r"(_mbar), "r"(_parity) : "memory"); \
    if (!_done) { \
        asm volatile("{\n\t.reg .pred P1;\n\t" \
            "WAIT_LOOP_%=:\n\t" \
            "mbarrier.try_wait.parity.acquire.cta.shared::cta.b64 P1, [%0], %1, 0x989680;\n\t" \
            "@P1 bra.uni WAIT_DONE_%=;\n\t" \
            "bra.uni WAIT_LOOP_%=;\n\t" \
            "WAIT_DONE_%=:\n\t}" :: "r"(_mbar), "r"(_parity) : "memory"); \
    } \
} while(0)

#define MBARRIER_WAIT_PARITY_RELAXED(mbar_smem_addr, phase_parity) do { \
    uint32_t _mbar = (uint32_t)(mbar_smem_addr); \
    uint32_t _parity = (uint32_t)(phase_parity); \
    uint32_t _done; \
    asm volatile("{\n\t.reg .pred p;\n\t" \
        "mbarrier.try_wait.parity.relaxed.cta.shared::cta.b64 p, [%1], %2, 0x989680;\n\t" \
        "selp.b32 %0, 1, 0, p;\n\t}" : "=r"(_done) : "r"(_mbar), "r"(_parity) : "memory"); \
    if (!_done) { \
        asm volatile("{\n\t.reg .pred P1;\n\t" \
            "WAIT_LOOP_%=:\n\t" \
            "mbarrier.try_wait.parity.relaxed.cta.shared::cta.b64 P1, [%0], %1, 0x989680;\n\t" \
            "@P1 bra.uni WAIT_DONE_%=;\n\t" \
            "bra.uni WAIT_LOOP_%=;\n\t" \
            "WAIT_DONE_%=:\n\t}" :: "r"(_mbar), "r"(_parity) : "memory"); \
    } \
} while(0)

__device__ __forceinline__ void bulk_g2s(uint32_t dst, const void* src,
                                         uint32_t bytes, uint32_t mbar) {
    asm volatile(
        "cp.async.bulk.shared::cluster.global.mbarrier::complete_tx::bytes [%0], [%1], %2, [%3];"
        :: "r"(dst), "l"(src), "r"(bytes), "r"(mbar) : "memory");
}

__device__ __forceinline__ void ldsm_x4(uint32_t addr, uint32_t& r0, uint32_t& r1,
                                        uint32_t& r2, uint32_t& r3) {
    asm volatile("ldmatrix.sync.aligned.m8n8.x4.shared.b16 {%0,%1,%2,%3}, [%4];"
        : "=r"(r0), "=r"(r1), "=r"(r2), "=r"(r3) : "r"(addr));
}

__device__ __forceinline__ void mma_bf16(float* c, uint32_t a0, uint32_t a1,
                                         uint32_t a2, uint32_t a3,
                                         uint32_t b0, uint32_t b1) {
    asm volatile(
        "mma.sync.aligned.m16n8k16.row.col.f32.bf16.bf16.f32 "
        "{%0,%1,%2,%3}, {%4,%5,%6,%7}, {%8,%9}, {%0,%1,%2,%3};"
        : "+f"(c[0]), "+f"(c[1]), "+f"(c[2]), "+f"(c[3])
        : "r"(a0), "r"(a1), "r"(a2), "r"(a3), "r"(b0), "r"(b1));
}

// ===========================================================================
// Scratch (static device globals; no allocations anywhere)
// 2-term storage everywhere: operand = [R, 2K] = hi tiles then lo tiles.
// ===========================================================================
__device__ float g_qkv[(size_t)SEQ * 3 * DMODEL];
__device__ float g_scores[(size_t)NH * SEQ * SEQ];
__device__ float g_ctx[(size_t)SEQ * DMODEL];
__device__ __align__(128) __nv_bfloat16 g_x2[(size_t)SEQ * 2 * DMODEL];
__device__ __align__(128) __nv_bfloat16 g_w1[(size_t)3 * DMODEL * 2 * DMODEL];
__device__ __align__(128) __nv_bfloat16 g_w2[(size_t)DMODEL * 2 * DMODEL];
__device__ __align__(128) __nv_bfloat16 g_q2[(size_t)NH * SEQ * 2 * HD];
__device__ __align__(128) __nv_bfloat16 g_k2[(size_t)NH * SEQ * 2 * HD];
__device__ __align__(128) __nv_bfloat16 g_vt[(size_t)NH * HD * 2 * SEQ];
__device__ __align__(128) __nv_bfloat16 g_p2[(size_t)NH * SEQ * 2 * SEQ];
__device__ __align__(128) __nv_bfloat16 g_c2[(size_t)SEQ * 2 * DMODEL];
__device__ float g_cos[SEQ * (HD / 2)];
__device__ float g_sin[SEQ * (HD / 2)];

// ===========================================================================
// Tiled/swizzled gmem layout: 128x64-bf16 tiles (16KB, SW128-swizzled),
// tile (rt, kt) at ((rt*ktiles + kt) << 14) bytes.
// Granule = 16B = 8 bf16 of one row; granule index k8 along K (k = k8*8).
// swizzled offset within tile: (r&127)*128 + (((k8&7)<<4) ^ ((r&7)<<4)).
// ===========================================================================
__device__ __forceinline__ size_t granule_off(int r, int k8, int ktiles) {
    int kt = k8 >> 3;
    uint32_t b = (uint32_t)((r & 127) * 128)
               + (((uint32_t)(k8 & 7) << 4) ^ ((uint32_t)(r & 7) << 4));
    return ((size_t)((r >> 7) * ktiles + kt) << 14) + b;
}

// split 8 fp32 into hi/lo bf16 granules
__device__ __forceinline__ void split8(const float* v, uint4& hi, uint4& lo) {
    uint32_t hw[4], lw[4];
    #pragma unroll
    for (int j = 0; j < 4; j++) {
        __nv_bfloat16 h0 = __float2bfloat16(v[2 * j]);
        __nv_bfloat16 h1 = __float2bfloat16(v[2 * j + 1]);
        __nv_bfloat16 l0 = __float2bfloat16(v[2 * j]     - __bfloat162float(h0));
        __nv_bfloat16 l1 = __float2bfloat16(v[2 * j + 1] - __bfloat162float(h1));
        hw[j] = (uint32_t)__bfloat16_as_ushort(h0) | ((uint32_t)__bfloat16_as_ushort(h1) << 16);
        lw[j] = (uint32_t)__bfloat16_as_ushort(l0) | ((uint32_t)__bfloat16_as_ushort(l1) << 16);
    }
    hi = make_uint4(hw[0], hw[1], hw[2], hw[3]);
    lo = make_uint4(lw[0], lw[1], lw[2], lw[3]);
}

// fp32 [R, K] (row stride ldin) -> tiled [R, 2K]; coalesced 16B granule writes
__global__ __launch_bounds__(256)
void split_tiles_g(const float* __restrict__ in, __nv_bfloat16* __restrict__ out,
                   int R, int K, int ldin, long long izs, long long ozs)
{
    int z = blockIdx.y;
    long long idx = (long long)blockIdx.x * 256 + threadIdx.x;
    int kg = K / 8;                         // granules per row per term
    long long tot = (long long)R * kg;
    if (idx >= tot) return;
    int r  = (int)(idx / kg);
    int k8 = (int)(idx - (long long)r * kg);
    const float* p = in + (long long)z * izs + (long long)r * ldin + k8 * 8;
    float v[8];
    float4 a = *(const float4*)p, b = *(const float4*)(p + 4);
    v[0]=a.x; v[1]=a.y; v[2]=a.z; v[3]=a.w; v[4]=b.x; v[5]=b.y; v[6]=b.z; v[7]=b.w;
    uint4 hi, lo; split8(v, hi, lo);
    char* o = (char*)(out + (long long)z * ozs);
    int ktiles = 2 * (K / 64);
    *(uint4*)(o + granule_off(r, k8, ktiles))          = hi;
    *(uint4*)(o + granule_off(r, k8 + K / 8, ktiles))  = lo;
}

// fp32 [K, N] (row stride ldin) -> tiled [N, 2K]; granule writes
__global__ __launch_bounds__(256)
void transpose_split_g(const float* __restrict__ in, __nv_bfloat16* __restrict__ out,
                       int K, int N, int ldin, long long izs, long long ozs)
{
    __shared__ float t[32][33];
    int z = blockIdx.z;
    const float* inz = in + (long long)z * izs;
    char* outz = (char*)(out + (long long)z * ozs);
    int n0 = blockIdx.x * 32, k0 = blockIdx.y * 32;
    int x = threadIdx.x, y = threadIdx.y;   // 32 x 8
    #pragma unroll
    for (int r = 0; r < 32; r += 8)
        t[y + r][x] = inz[(long long)(k0 + y + r) * ldin + n0 + x];
    __syncthreads();
    int tt = y * 32 + x;
    if (tt < 128) {
        int nn = tt >> 2, g = tt & 3;
        float v[8];
        #pragma unroll
        for (int j = 0; j < 8; j++) v[j] = t[g * 8 + j][nn];
        uint4 hi, lo; split8(v, hi, lo);
        int ktiles = 2 * (K / 64);
        int n = n0 + nn, k8 = (k0 >> 3) + g;
        *(uint4*)(outz + granule_off(n, k8, ktiles))         = hi;
        *(uint4*)(outz + granule_off(n, k8 + K / 8, ktiles)) = lo;
    }
}

// ===========================================================================
// mma.sync bf16 GEMM with 3-term double-bf16 chunks over 2-term storage.
// chunk c in [0, 3*nk0): term t = c/nk0, k = c%nk0;
//   A tile = (t==1 ? nk0 : 0)+k   (hi, lo, hi)
//   B tile = (t==2 ? nk0 : 0)+k   (hi, hi, lo)
// BM=256, BN=128, BK=64. 256 threads (8 warps, 4x2), warp tile 64x64.
// ===========================================================================
#define GST 3
#define STAGE_BYTES 49152
#define GEMM_DYN_SMEM (GST * STAGE_BYTES + 1024)

__global__ __launch_bounds__(256, 1)
void gemm_mma(const __nv_bfloat16* __restrict__ A, const __nv_bfloat16* __restrict__ B,
              float* __restrict__ C, int nk0, int ldc,
              long long Az, long long Bz, long long Cz, float alpha)
{
    extern __shared__ char dyn[];
    __shared__ __align__(8) unsigned long long s_mbar[2 * GST];

    const int tid  = threadIdx.x;
    const int wid  = tid >> 5;
    const int lane = tid & 31;
    const int wm = wid >> 1, wn = wid & 1;
    const int mt2 = blockIdx.x, ntb = blockIdx.y, z = blockIdx.z;
    const int nk = 3 * nk0;

    uint32_t stages = (smem_u32(dyn) + 1023u) & ~1023u;
    uint32_t mb = smem_u32(s_mbar);

    if (tid == 0) {
        #pragma unroll
        for (int i = 0; i < GST; i++)  MBARRIER_INIT(mb + i * 8, 1);
        #pragma unroll
        for (int i = GST; i < 2 * GST; i++) MBARRIER_INIT(mb + i * 8, 8);
    }
    __syncthreads();

    const char* Ab = (const char*)A + (size_t)z * Az * 2 + (((size_t)(2 * mt2) * (2 * nk0)) << 14);
    const char* Bb = (const char*)B + (size_t)z * Bz * 2 + (((size_t)ntb * (2 * nk0)) << 14);
    const size_t Astride = ((size_t)(2 * nk0) << 14);

    if (tid == 0) {
        for (int c = 0; c < GST - 1 && c < nk; c++) {
            int t = c / nk0, k = c % nk0;
            size_t ao = ((size_t)((t == 1 ? nk0 : 0) + k)) << 14;
            size_t bo = ((size_t)((t == 2 ? nk0 : 0) + k)) << 14;
            uint32_t st = stages + c * STAGE_BYTES;
            MBARRIER_EXPECT_TX(mb + c * 8, STAGE_BYTES);
            bulk_g2s(st,         Ab + ao,           16384, mb + c * 8);
            bulk_g2s(st + 16384, Ab + Astride + ao, 16384, mb + c * 8);
            bulk_g2s(st + 32768, Bb + bo,           16384, mb + c * 8);
        }
    }

    const int r_a = wm * 64 + (lane & 15);
    const uint32_t a_rowoff = ((uint32_t)(r_a >> 7) << 14) + (uint32_t)(r_a & 127) * 128;
    const uint32_t a_sw = (uint32_t)(r_a & 7) << 4;
    const uint32_t cbA  = (uint32_t)(lane >> 4) * 16;

    const int r_b = wn * 64 + (lane & 7) + ((lane >> 4) & 1) * 8;
    const uint32_t b_rowoff = 32768u + (uint32_t)r_b * 128;
    const uint32_t b_sw = (uint32_t)(r_b & 7) << 4;
    const uint32_t cbB  = (uint32_t)((lane >> 3) & 1) * 16;

    float acc[4][8][4];
    #pragma unroll
    for (int i = 0; i < 4; i++)
        #pragma unroll
        for (int j = 0; j < 8; j++)
            #pragma unroll
            for (int q = 0; q < 4; q++) acc[i][j][q] = 0.f;

    for (int c = 0; c < nk; c++) {
        if (tid == 0) {
            int jc = c + GST - 1;
            if (jc < nk) {
                int t = jc / nk0, k = jc % nk0;
                size_t ao = ((size_t)((t == 1 ? nk0 : 0) + k)) << 14;
                size_t bo = ((size_t)((t == 2 ? nk0 : 0) + k)) << 14;
                int s2 = jc % GST;
                if (jc >= GST)
                    MBARRIER_WAIT_PARITY_RELAXED(mb + (GST + s2) * 8, ((jc / GST) - 1) & 1);
                uint32_t st = stages + s2 * STAGE_BYTES;
                MBARRIER_EXPECT_TX(mb + s2 * 8, STAGE_BYTES);
                bulk_g2s(st,         Ab + ao,           16384, mb + s2 * 8);
                bulk_g2s(st + 16384, Ab + Astride + ao, 16384, mb + s2 * 8);
                bulk_g2s(st + 32768, Bb + bo,           16384, mb + s2 * 8);
            }
        }

        int s = c % GST;
        MBARRIER_WAIT_PARITY(mb + s * 8, (c / GST) & 1);
        uint32_t st = stages + s * STAGE_BYTES;
        uint32_t abase = st + a_rowoff;
        uint32_t bbase = st + b_rowoff;

        #pragma unroll
        for (int kk = 0; kk < 4; kk++) {
            uint32_t a[4][4];
            uint32_t acol = a_sw ^ (cbA + kk * 32);
            #pragma unroll
            for (int mt = 0; mt < 4; mt++)
                ldsm_x4(abase + mt * 2048 + acol, a[mt][0], a[mt][1], a[mt][2], a[mt][3]);

            uint32_t b[8][2];
            uint32_t bcol = b_sw ^ (cbB + kk * 32);
            #pragma unroll
            for (int u = 0; u < 4; u++) {
                uint32_t r0, r1, r2, r3;
                ldsm_x4(bbase + u * 2048 + bcol, r0, r1, r2, r3);
                b[2 * u][0] = r0; b[2 * u][1] = r1;
                b[2 * u + 1][0] = r2; b[2 * u + 1][1] = r3;
            }

            #pragma unroll
            for (int mt = 0; mt < 4; mt++)
                #pragma unroll
                for (int nt = 0; nt < 8; nt++)
                    mma_bf16(acc[mt][nt], a[mt][0], a[mt][1], a[mt][2], a[mt][3],
                             b[nt][0], b[nt][1]);
        }

        if (lane == 0) MBARRIER_ARRIVE(mb + (GST + s) * 8);
    }

    float* Cb = C + (size_t)z * Cz;
    const int row0 = mt2 * 256 + wm * 64;
    const int col0 = ntb * 128 + wn * 64;
    #pragma unroll
    for (int mt = 0; mt < 4; mt++) {
        int r = row0 + mt * 16 + (lane >> 2);
        #pragma unroll
        for (int nt = 0; nt < 8; nt++) {
            int cc = col0 + nt * 8 + (lane & 3) * 2;
            float2 v0 = { acc[mt][nt][0] * alpha, acc[mt][nt][1] * alpha };
            float2 v1 = { acc[mt][nt][2] * alpha, acc[mt][nt][3] * alpha };
            *(float2*)(Cb + (size_t)r * ldc + cc)       = v0;
            *(float2*)(Cb + (size_t)(r + 8) * ldc + cc) = v1;
        }
    }
}

// ===========================================================================
// RoPE table + fused rope->split for Q and K (reads qkv, writes q2/k2 tiles)
// ===========================================================================
__global__ void build_rope_table()
{
    int idx = blockIdx.x * blockDim.x + threadIdx.x;
    if (idx >= SEQ * (HD / 2)) return;
    int i = idx % (HD / 2);
    int s = idx / (HD / 2);
    double freq_d = pow(10000.0, -(double)(2 * i) / (double)HD);
    float freq  = (float)freq_d;
    float angle = (float)s * freq;
    g_cos[idx] = (float)cos((double)angle);
    g_sin[idx] = (float)sin((double)angle);
}

__global__ __launch_bounds__(256)
void rope_split(const float* __restrict__ qkv,
                __nv_bfloat16* __restrict__ q2, __nv_bfloat16* __restrict__ k2)
{
    int idx = blockIdx.x * 256 + threadIdx.x;        // (s, h, j) j = granule 0..15
    if (idx >= SEQ * NH * 16) return;
    int j = idx & 15;
    int h = (idx >> 4) & 31;
    int s = idx >> 9;

    const float* qp = qkv + (long long)s * (3 * DMODEL) + h * HD + j * 8;
    float q[8], k[8];
    {
        float4 a = *(const float4*)qp, b = *(const float4*)(qp + 4);
        q[0]=a.x; q[1]=a.y; q[2]=a.z; q[3]=a.w; q[4]=b.x; q[5]=b.y; q[6]=b.z; q[7]=b.w;
        float4 c = *(const float4*)(qp + DMODEL), d = *(const float4*)(qp + DMODEL + 4);
        k[0]=c.x; k[1]=c.y; k[2]=c.z; k[3]=c.w; k[4]=d.x; k[5]=d.y; k[6]=d.z; k[7]=d.w;
    }
    #pragma unroll
    for (int p = 0; p < 4; p++) {
        int i = j * 4 + p;
        float c  = g_cos[s * 64 + i];
        float sn = g_sin[s * 64 + i];
        float q0 = q[2*p], q1 = q[2*p+1];
        q[2*p]   = q0 * c - q1 * sn;
        q[2*p+1] = q0 * sn + q1 * c;
        float k0 = k[2*p], k1 = k[2*p+1];
        k[2*p]   = k0 * c - k1 * sn;
        k[2*p+1] = k0 * sn + k1 * c;
    }
    uint4 qhi, qlo, khi, klo;
    split8(q, qhi, qlo);
    split8(k, khi, klo);
    char* qo = (char*)(q2 + (long long)h * SEQ * 2 * HD);
    char* ko = (char*)(k2 + (long long)h * SEQ * 2 * HD);
    *(uint4*)(qo + granule_off(s, j, 4))      = qhi;
    *(uint4*)(qo + granule_off(s, j + 16, 4)) = qlo;
    *(uint4*)(ko + granule_off(s, j, 4))      = khi;
    *(uint4*)(ko + granule_off(s, j + 16, 4)) = klo;
}

// ===========================================================================
// Softmax rows -> P tiled [2048, 2*2048] per head, granule writes
// ===========================================================================
__global__ __launch_bounds__(256)
void softmax_p(const float* __restrict__ scores, __nv_bfloat16* __restrict__ P)
{
    long long row = blockIdx.x;
    int h = (int)(row >> 11);
    int r = (int)(row & 2047);
    const float* p = scores + row * (long long)SEQ;
    int t = threadIdx.x;

    float v[8];
    const float4* p4 = (const float4*)(p + t * 8);
    float4 va = p4[0], vb = p4[1];
    v[0] = va.x; v[1] = va.y; v[2] = va.z; v[3] = va.w;
    v[4] = vb.x; v[5] = vb.y; v[6] = vb.z; v[7] = vb.w;

    float m = -1e30f;
    #pragma unroll
    for (int j = 0; j < 8; j++) m = fmaxf(m, v[j]);
    #pragma unroll
    for (int o = 16; o > 0; o >>= 1) m = fmaxf(m, __shfl_xor_sync(0xffffffffu, m, o));

    __shared__ float red[8];
    if ((t & 31) == 0) red[t >> 5] = m;
    __syncthreads();
    float bm = red[0];
    #pragma unroll
    for (int i = 1; i < 8; i++) bm = fmaxf(bm, red[i]);

    float s = 0.f;
    #pragma unroll
    for (int j = 0; j < 8; j++) { v[j] = expf(v[j] - bm); s += v[j]; }
    #pragma unroll
    for (int o = 16; o > 0; o >>= 1) s += __shfl_xor_sync(0xffffffffu, s, o);
    __syncthreads();
    if ((t & 31) == 0) red[t >> 5] = s;
    __syncthreads();
    float bs = 0.f;
    #pragma unroll
    for (int i = 0; i < 8; i++) bs += red[i];
    float inv = 1.0f / bs;
    #pragma unroll
    for (int j = 0; j < 8; j++) v[j] *= inv;

    uint4 hi, lo; split8(v, hi, lo);
    char* Pb = (char*)(P + (long long)h * SEQ * 2 * SEQ);
    *(uint4*)(Pb + granule_off(r, t, 64))       = hi;
    *(uint4*)(Pb + granule_off(r, t + 256, 64)) = lo;
}

// ===========================================================================
extern "C" void kernel_launch(void* const* d_in, const int* in_sizes, int n_in,
                              void* d_out, int out_size)
{
    const float* hidden = (const float*)d_in[0];   // [2048, 4096]
    const float* wqkv   = (const float*)d_in[1];   // [4096, 12288]
    const float* wo     = (const float*)d_in[2];   // [4096, 4096]
    float* out = (float*)d_out;                    // [2048, 4096]

    float *qkv, *scores, *ctx;
    __nv_bfloat16 *x2, *w1, *w2, *q2, *k2, *vt, *p2, *c2;
    cudaGetSymbolAddress((void**)&qkv,    g_qkv);
    cudaGetSymbolAddress((void**)&scores, g_scores);
    cudaGetSymbolAddress((void**)&ctx,    g_ctx);
    cudaGetSymbolAddress((void**)&x2, g_x2);
    cudaGetSymbolAddress((void**)&w1, g_w1);
    cudaGetSymbolAddress((void**)&w2, g_w2);
    cudaGetSymbolAddress((void**)&q2, g_q2);
    cudaGetSymbolAddress((void**)&k2, g_k2);
    cudaGetSymbolAddress((void**)&vt, g_vt);
    cudaGetSymbolAddress((void**)&p2, g_p2);
    cudaGetSymbolAddress((void**)&c2, g_c2);

    cudaFuncSetAttribute(gemm_mma, cudaFuncAttributeMaxDynamicSharedMemorySize, GEMM_DYN_SMEM);

    // ---- operand conversion (split + pre-swizzle, 2-term, coalesced) ----
    split_tiles_g<<<dim3((2048 * 512 + 255) / 256, 1), 256>>>(
        hidden, x2, 2048, 4096, 4096, 0, 0);
    transpose_split_g<<<dim3(12288 / 32, 4096 / 32, 1), dim3(32, 8)>>>(
        wqkv, w1, 4096, 12288, 12288, 0, 0);
    transpose_split_g<<<dim3(4096 / 32, 4096 / 32, 1), dim3(32, 8)>>>(
        wo, w2, 4096, 4096, 4096, 0, 0);

    // ---- QKV GEMM: [2048, 12288] = X @ Wqkv  (nk0 = 64) ----
    gemm_mma<<<dim3(8, 96, 1), 256, GEMM_DYN_SMEM>>>(
        x2, w1, qkv, 64, 12288, 0, 0, 0, 1.0f);

    // ---- fused RoPE + Q/K split ----
    build_rope_table<<<(SEQ * (HD / 2) + 255) / 256, 256>>>();
    rope_split<<<(SEQ * NH * 16 + 255) / 256, 256>>>(qkv, q2, k2);

    // ---- V^T split per head ----
    transpose_split_g<<<dim3(128 / 32, 2048 / 32, NH), dim3(32, 8)>>>(
        qkv + 2 * DMODEL, vt, 2048, 128, 3 * DMODEL,
        /*izs=*/HD, /*ozs=*/(long long)HD * 2 * SEQ);

    // ---- scores[h] = (1/sqrt(HD)) * Q[h] @ K[h]^T  (nk0 = 2) ----
    gemm_mma<<<dim3(8, 16, NH), 256, GEMM_DYN_SMEM>>>(
        q2, k2, scores, 2, SEQ,
        (long long)SEQ * 2 * HD, (long long)SEQ * 2 * HD, (long long)SEQ * SEQ,
        0.08838834764831845f);

    // ---- softmax -> P tiled 2-term ----
    softmax_p<<<NH * SEQ, 256>>>(scores, p2);

    // ---- ctx[h] = P[h] @ V[h]  (nk0 = 32, N = 128) ----
    gemm_mma<<<dim3(8, 1, NH), 256, GEMM_DYN_SMEM>>>(
        p2, vt, ctx, 32, DMODEL,
        (long long)SEQ * 2 * SEQ, (long long)HD * 2 * SEQ, /*Cz=*/HD,
        1.0f);

    // ---- ctx split ----
    split_tiles_g<<<dim3((2048 * 512 + 255) / 256, 1), 256>>>(
        ctx, c2, 2048, 4096, 4096, 0, 0);

    // ---- out = ctx @ Wo  (nk0 = 64) ----
    gemm_mma<<<dim3(8, 32, 1), 256, GEMM_DYN_SMEM>>>(
        c2, w2, out, 64, 4096, 0, 0, 0, 1.0f);
}

// round 8
// speedup vs baseline: 3.5861x; 1.0138x over previous
#include <cuda_runtime.h>
#include <cuda_bf16.h>
#include <math.h>
#include <stdint.h>

#define SEQ 2048
#define DMODEL 4096
#define NH 32
#define HD 128

// ===========================================================================
// PTX helpers (sm_103-safe subset)
// ===========================================================================
__device__ __forceinline__ uint32_t smem_u32(const void* p) {
    uint32_t a;
    asm("{ .reg .u64 t; cvta.to.shared.u64 t, %1; cvt.u32.u64 %0, t; }" : "=r"(a) : "l"(p));
    return a;
}
#define MBARRIER_INIT(addr, cnt) \
    asm volatile("mbarrier.init.shared.b64 [%0], %1;" :: "r"((uint32_t)(addr)), "r"((uint32_t)(cnt)) : "memory")
#define MBARRIER_EXPECT_TX(addr, bytes) \
    asm volatile("mbarrier.arrive.expect_tx.shared.b64 _, [%0], %1;" :: "r"((uint32_t)(addr)), "r"((uint32_t)(bytes)) : "memory")
#define MBARRIER_ARRIVE(addr) \
    asm volatile("mbarrier.arrive.shared.b64 _, [%0];" :: "r"((uint32_t)(addr)) : "memory")

#define MBARRIER_WAIT_PARITY(mbar_smem_addr, phase_parity) do { \
    uint32_t _mbar = (uint32_t)(mbar_smem_addr); \
    uint32_t _parity = (uint32_t)(phase_parity); \
    uint32_t _done; \
    asm volatile("{\n\t.reg .pred p;\n\t" \
        "mbarrier.try_wait.parity.acquire.cta.shared::cta.b64 p, [%1], %2;\n\t" \
        "selp.b32 %0, 1, 0, p;\n\t}" : "=r"(_done) : "r"(_mbar), "r"(_parity) : "memory"); \
    if (!_done) { \
        asm volatile("{\n\t.reg .pred P1;\n\t" \
            "WAIT_LOOP_%=:\n\t" \
            "mbarrier.try_wait.parity.acquire.cta.shared::cta.b64 P1, [%0], %1, 0x989680;\n\t" \
            "@P1 bra.uni WAIT_DONE_%=;\n\t" \
            "bra.uni WAIT_LOOP_%=;\n\t" \
            "WAIT_DONE_%=:\n\t}" :: "r"(_mbar), "r"(_parity) : "memory"); \
    } \
} while(0)

#define MBARRIER_WAIT_PARITY_RELAXED(mbar_smem_addr, phase_parity) do { \
    uint32_t _mbar = (uint32_t)(mbar_smem_addr); \
    uint32_t _parity = (uint32_t)(phase_parity); \
    uint32_t _done; \
    asm volatile("{\n\t.reg .pred p;\n\t" \
        "mbarrier.try_wait.parity.relaxed.cta.shared::cta.b64 p, [%1], %2, 0x989680;\n\t" \
        "selp.b32 %0, 1, 0, p;\n\t}" : "=r"(_done) : "r"(_mbar), "r"(_parity) : "memory"); \
    if (!_done) { \
        asm volatile("{\n\t.reg .pred P1;\n\t" \
            "WAIT_LOOP_%=:\n\t" \
            "mbarrier.try_wait.parity.relaxed.cta.shared::cta.b64 P1, [%0], %1, 0x989680;\n\t" \
            "@P1 bra.uni WAIT_DONE_%=;\n\t" \
            "bra.uni WAIT_LOOP_%=;\n\t" \
            "WAIT_DONE_%=:\n\t}" :: "r"(_mbar), "r"(_parity) : "memory"); \
    } \
} while(0)

__device__ __forceinline__ void bulk_g2s(uint32_t dst, const void* src,
                                         uint32_t bytes, uint32_t mbar) {
    asm volatile(
        "cp.async.bulk.shared::cluster.global.mbarrier::complete_tx::bytes [%0], [%1], %2, [%3];"
        :: "r"(dst), "l"(src), "r"(bytes), "r"(mbar) : "memory");
}

__device__ __forceinline__ void ldsm_x4(uint32_t addr, uint32_t& r0, uint32_t& r1,
                                        uint32_t& r2, uint32_t& r3) {
    asm volatile("ldmatrix.sync.aligned.m8n8.x4.shared.b16 {%0,%1,%2,%3}, [%4];"
        : "=r"(r0), "=r"(r1), "=r"(r2), "=r"(r3) : "r"(addr));
}

__device__ __forceinline__ void mma_bf16(float* c, uint32_t a0, uint32_t a1,
                                         uint32_t a2, uint32_t a3,
                                         uint32_t b0, uint32_t b1) {
    asm volatile(
        "mma.sync.aligned.m16n8k16.row.col.f32.bf16.bf16.f32 "
        "{%0,%1,%2,%3}, {%4,%5,%6,%7}, {%8,%9}, {%0,%1,%2,%3};"
        : "+f"(c[0]), "+f"(c[1]), "+f"(c[2]), "+f"(c[3])
        : "r"(a0), "r"(a1), "r"(a2), "r"(a3), "r"(b0), "r"(b1));
}

__device__ __forceinline__ float ex2f(float x) {
    float r;
    asm("ex2.approx.f32 %0, %1;" : "=f"(r) : "f"(x));
    return r;
}

// ===========================================================================
// Scratch (static device globals; no allocations anywhere)
// ===========================================================================
__device__ float g_qkv[(size_t)SEQ * 3 * DMODEL];
__device__ float g_ctx[(size_t)SEQ * DMODEL];
__device__ __align__(128) __nv_bfloat16 g_x2[(size_t)SEQ * 2 * DMODEL];
__device__ __align__(128) __nv_bfloat16 g_w1[(size_t)3 * DMODEL * 2 * DMODEL];
__device__ __align__(128) __nv_bfloat16 g_w2[(size_t)DMODEL * 2 * DMODEL];
__device__ __align__(128) __nv_bfloat16 g_q2[(size_t)NH * SEQ * 2 * HD];
__device__ __align__(128) __nv_bfloat16 g_k2[(size_t)NH * SEQ * 2 * HD];
__device__ __align__(128) __nv_bfloat16 g_vt[(size_t)NH * HD * 2 * SEQ];
__device__ __align__(128) __nv_bfloat16 g_c2[(size_t)SEQ * 2 * DMODEL];
__device__ float g_cos[SEQ * (HD / 2)];
__device__ float g_sin[SEQ * (HD / 2)];

// ===========================================================================
// Tiled/swizzled gmem layout: 128x64-bf16 tiles (16KB, SW128-swizzled)
// ===========================================================================
__device__ __forceinline__ size_t granule_off(int r, int k8, int ktiles) {
    int kt = k8 >> 3;
    uint32_t b = (uint32_t)((r & 127) * 128)
               + (((uint32_t)(k8 & 7) << 4) ^ ((uint32_t)(r & 7) << 4));
    return ((size_t)((r >> 7) * ktiles + kt) << 14) + b;
}

__device__ __forceinline__ void split8(const float* v, uint4& hi, uint4& lo) {
    uint32_t hw[4], lw[4];
    #pragma unroll
    for (int j = 0; j < 4; j++) {
        __nv_bfloat16 h0 = __float2bfloat16(v[2 * j]);
        __nv_bfloat16 h1 = __float2bfloat16(v[2 * j + 1]);
        __nv_bfloat16 l0 = __float2bfloat16(v[2 * j]     - __bfloat162float(h0));
        __nv_bfloat16 l1 = __float2bfloat16(v[2 * j + 1] - __bfloat162float(h1));
        hw[j] = (uint32_t)__bfloat16_as_ushort(h0) | ((uint32_t)__bfloat16_as_ushort(h1) << 16);
        lw[j] = (uint32_t)__bfloat16_as_ushort(l0) | ((uint32_t)__bfloat16_as_ushort(l1) << 16);
    }
    hi = make_uint4(hw[0], hw[1], hw[2], hw[3]);
    lo = make_uint4(lw[0], lw[1], lw[2], lw[3]);
}

__global__ __launch_bounds__(256)
void split_tiles_g(const float* __restrict__ in, __nv_bfloat16* __restrict__ out,
                   int R, int K, int ldin, long long izs, long long ozs)
{
    int z = blockIdx.y;
    long long idx = (long long)blockIdx.x * 256 + threadIdx.x;
    int kg = K / 8;
    long long tot = (long long)R * kg;
    if (idx >= tot) return;
    int r  = (int)(idx / kg);
    int k8 = (int)(idx - (long long)r * kg);
    const float* p = in + (long long)z * izs + (long long)r * ldin + k8 * 8;
    float v[8];
    float4 a = *(const float4*)p, b = *(const float4*)(p + 4);
    v[0]=a.x; v[1]=a.y; v[2]=a.z; v[3]=a.w; v[4]=b.x; v[5]=b.y; v[6]=b.z; v[7]=b.w;
    uint4 hi, lo; split8(v, hi, lo);
    char* o = (char*)(out + (long long)z * ozs);
    int ktiles = 2 * (K / 64);
    *(uint4*)(o + granule_off(r, k8, ktiles))          = hi;
    *(uint4*)(o + granule_off(r, k8 + K / 8, ktiles))  = lo;
}

__global__ __launch_bounds__(256)
void transpose_split_g(const float* __restrict__ in, __nv_bfloat16* __restrict__ out,
                       int K, int N, int ldin, long long izs, long long ozs)
{
    __shared__ float t[32][33];
    int z = blockIdx.z;
    const float* inz = in + (long long)z * izs;
    char* outz = (char*)(out + (long long)z * ozs);
    int n0 = blockIdx.x * 32, k0 = blockIdx.y * 32;
    int x = threadIdx.x, y = threadIdx.y;   // 32 x 8
    #pragma unroll
    for (int r = 0; r < 32; r += 8)
        t[y + r][x] = inz[(long long)(k0 + y + r) * ldin + n0 + x];
    __syncthreads();
    int tt = y * 32 + x;
    if (tt < 128) {
        int nn = tt >> 2, g = tt & 3;
        float v[8];
        #pragma unroll
        for (int j = 0; j < 8; j++) v[j] = t[g * 8 + j][nn];
        uint4 hi, lo; split8(v, hi, lo);
        int ktiles = 2 * (K / 64);
        int n = n0 + nn, k8 = (k0 >> 3) + g;
        *(uint4*)(outz + granule_off(n, k8, ktiles))         = hi;
        *(uint4*)(outz + granule_off(n, k8 + K / 8, ktiles)) = lo;
    }
}

// ===========================================================================
// mma.sync bf16 GEMM (3-term chunks over 2-term storage) — unchanged core
// ===========================================================================
#define GST 3
#define STAGE_BYTES 49152
#define GEMM_DYN_SMEM (GST * STAGE_BYTES + 1024)

__global__ __launch_bounds__(256, 1)
void gemm_mma(const __nv_bfloat16* __restrict__ A, const __nv_bfloat16* __restrict__ B,
              float* __restrict__ C, int nk0, int ldc,
              long long Az, long long Bz, long long Cz, float alpha)
{
    extern __shared__ char dyn[];
    __shared__ __align__(8) unsigned long long s_mbar[2 * GST];

    const int tid  = threadIdx.x;
    const int wid  = tid >> 5;
    const int lane = tid & 31;
    const int wm = wid >> 1, wn = wid & 1;
    const int mt2 = blockIdx.x, ntb = blockIdx.y, z = blockIdx.z;
    const int nk = 3 * nk0;

    uint32_t stages = (smem_u32(dyn) + 1023u) & ~1023u;
    uint32_t mb = smem_u32(s_mbar);

    if (tid == 0) {
        #pragma unroll
        for (int i = 0; i < GST; i++)  MBARRIER_INIT(mb + i * 8, 1);
        #pragma unroll
        for (int i = GST; i < 2 * GST; i++) MBARRIER_INIT(mb + i * 8, 8);
    }
    __syncthreads();

    const char* Ab = (const char*)A + (size_t)z * Az * 2 + (((size_t)(2 * mt2) * (2 * nk0)) << 14);
    const char* Bb = (const char*)B + (size_t)z * Bz * 2 + (((size_t)ntb * (2 * nk0)) << 14);
    const size_t Astride = ((size_t)(2 * nk0) << 14);

    if (tid == 0) {
        for (int c = 0; c < GST - 1 && c < nk; c++) {
            int t = c / nk0, k = c % nk0;
            size_t ao = ((size_t)((t == 1 ? nk0 : 0) + k)) << 14;
            size_t bo = ((size_t)((t == 2 ? nk0 : 0) + k)) << 14;
            uint32_t st = stages + c * STAGE_BYTES;
            MBARRIER_EXPECT_TX(mb + c * 8, STAGE_BYTES);
            bulk_g2s(st,         Ab + ao,           16384, mb + c * 8);
            bulk_g2s(st + 16384, Ab + Astride + ao, 16384, mb + c * 8);
            bulk_g2s(st + 32768, Bb + bo,           16384, mb + c * 8);
        }
    }

    const int r_a = wm * 64 + (lane & 15);
    const uint32_t a_rowoff = ((uint32_t)(r_a >> 7) << 14) + (uint32_t)(r_a & 127) * 128;
    const uint32_t a_sw = (uint32_t)(r_a & 7) << 4;
    const uint32_t cbA  = (uint32_t)(lane >> 4) * 16;

    const int r_b = wn * 64 + (lane & 7) + ((lane >> 4) & 1) * 8;
    const uint32_t b_rowoff = 32768u + (uint32_t)r_b * 128;
    const uint32_t b_sw = (uint32_t)(r_b & 7) << 4;
    const uint32_t cbB  = (uint32_t)((lane >> 3) & 1) * 16;

    float acc[4][8][4];
    #pragma unroll
    for (int i = 0; i < 4; i++)
        #pragma unroll
        for (int j = 0; j < 8; j++)
            #pragma unroll
            for (int q = 0; q < 4; q++) acc[i][j][q] = 0.f;

    for (int c = 0; c < nk; c++) {
        if (tid == 0) {
            int jc = c + GST - 1;
            if (jc < nk) {
                int t = jc / nk0, k = jc % nk0;
                size_t ao = ((size_t)((t == 1 ? nk0 : 0) + k)) << 14;
                size_t bo = ((size_t)((t == 2 ? nk0 : 0) + k)) << 14;
                int s2 = jc % GST;
                if (jc >= GST)
                    MBARRIER_WAIT_PARITY_RELAXED(mb + (GST + s2) * 8, ((jc / GST) - 1) & 1);
                uint32_t st = stages + s2 * STAGE_BYTES;
                MBARRIER_EXPECT_TX(mb + s2 * 8, STAGE_BYTES);
                bulk_g2s(st,         Ab + ao,           16384, mb + s2 * 8);
                bulk_g2s(st + 16384, Ab + Astride + ao, 16384, mb + s2 * 8);
                bulk_g2s(st + 32768, Bb + bo,           16384, mb + s2 * 8);
            }
        }

        int s = c % GST;
        MBARRIER_WAIT_PARITY(mb + s * 8, (c / GST) & 1);
        uint32_t st = stages + s * STAGE_BYTES;
        uint32_t abase = st + a_rowoff;
        uint32_t bbase = st + b_rowoff;

        #pragma unroll
        for (int kk = 0; kk < 4; kk++) {
            uint32_t a[4][4];
            uint32_t acol = a_sw ^ (cbA + kk * 32);
            #pragma unroll
            for (int mt = 0; mt < 4; mt++)
                ldsm_x4(abase + mt * 2048 + acol, a[mt][0], a[mt][1], a[mt][2], a[mt][3]);

            uint32_t b[8][2];
            uint32_t bcol = b_sw ^ (cbB + kk * 32);
            #pragma unroll
            for (int u = 0; u < 4; u++) {
                uint32_t r0, r1, r2, r3;
                ldsm_x4(bbase + u * 2048 + bcol, r0, r1, r2, r3);
                b[2 * u][0] = r0; b[2 * u][1] = r1;
                b[2 * u + 1][0] = r2; b[2 * u + 1][1] = r3;
            }

            #pragma unroll
            for (int mt = 0; mt < 4; mt++)
                #pragma unroll
                for (int nt = 0; nt < 8; nt++)
                    mma_bf16(acc[mt][nt], a[mt][0], a[mt][1], a[mt][2], a[mt][3],
                             b[nt][0], b[nt][1]);
        }

        if (lane == 0) MBARRIER_ARRIVE(mb + (GST + s) * 8);
    }

    float* Cb = C + (size_t)z * Cz;
    const int row0 = mt2 * 256 + wm * 64;
    const int col0 = ntb * 128 + wn * 64;
    #pragma unroll
    for (int mt = 0; mt < 4; mt++) {
        int r = row0 + mt * 16 + (lane >> 2);
        #pragma unroll
        for (int nt = 0; nt < 8; nt++) {
            int cc = col0 + nt * 8 + (lane & 3) * 2;
            float2 v0 = { acc[mt][nt][0] * alpha, acc[mt][nt][1] * alpha };
            float2 v1 = { acc[mt][nt][2] * alpha, acc[mt][nt][3] * alpha };
            *(float2*)(Cb + (size_t)r * ldc + cc)       = v0;
            *(float2*)(Cb + (size_t)(r + 8) * ldc + cc) = v1;
        }
    }
}

// ===========================================================================
// RoPE table + fused rope->split. Q gets 1/sqrt(HD) folded in.
// ===========================================================================
__global__ void build_rope_table()
{
    int idx = blockIdx.x * blockDim.x + threadIdx.x;
    if (idx >= SEQ * (HD / 2)) return;
    int i = idx % (HD / 2);
    int s = idx / (HD / 2);
    double freq_d = pow(10000.0, -(double)(2 * i) / (double)HD);
    float freq  = (float)freq_d;
    float angle = (float)s * freq;
    g_cos[idx] = (float)cos((double)angle);
    g_sin[idx] = (float)sin((double)angle);
}

__global__ __launch_bounds__(256)
void rope_split(const float* __restrict__ qkv,
                __nv_bfloat16* __restrict__ q2, __nv_bfloat16* __restrict__ k2)
{
    const float SCALE = 0.08838834764831845f;
    int idx = blockIdx.x * 256 + threadIdx.x;        // (s, h, j)
    if (idx >= SEQ * NH * 16) return;
    int j = idx & 15;
    int h = (idx >> 4) & 31;
    int s = idx >> 9;

    const float* qp = qkv + (long long)s * (3 * DMODEL) + h * HD + j * 8;
    float q[8], k[8];
    {
        float4 a = *(const float4*)qp, b = *(const float4*)(qp + 4);
        q[0]=a.x; q[1]=a.y; q[2]=a.z; q[3]=a.w; q[4]=b.x; q[5]=b.y; q[6]=b.z; q[7]=b.w;
        float4 c = *(const float4*)(qp + DMODEL), d = *(const float4*)(qp + DMODEL + 4);
        k[0]=c.x; k[1]=c.y; k[2]=c.z; k[3]=c.w; k[4]=d.x; k[5]=d.y; k[6]=d.z; k[7]=d.w;
    }
    #pragma unroll
    for (int p = 0; p < 4; p++) {
        int i = j * 4 + p;
        float c  = g_cos[s * 64 + i];
        float sn = g_sin[s * 64 + i];
        float q0 = q[2*p], q1 = q[2*p+1];
        q[2*p]   = (q0 * c - q1 * sn) * SCALE;
        q[2*p+1] = (q0 * sn + q1 * c) * SCALE;
        float k0 = k[2*p], k1 = k[2*p+1];
        k[2*p]   = k0 * c - k1 * sn;
        k[2*p+1] = k0 * sn + k1 * c;
    }
    uint4 qhi, qlo, khi, klo;
    split8(q, qhi, qlo);
    split8(k, khi, klo);
    char* qo = (char*)(q2 + (long long)h * SEQ * 2 * HD);
    char* ko = (char*)(k2 + (long long)h * SEQ * 2 * HD);
    *(uint4*)(qo + granule_off(s, j, 4))      = qhi;
    *(uint4*)(qo + granule_off(s, j + 16, 4)) = qlo;
    *(uint4*)(ko + granule_off(s, j, 4))      = khi;
    *(uint4*)(ko + granule_off(s, j + 16, 4)) = klo;
}

// ===========================================================================
// Flash attention: one CTA = (128 Q rows, head). S and O in registers,
// online softmax, P re-split in registers. K/V staged by bulk copies.
// smem: Q 64KB persistent | K 64KB | V 64KB.
// 8 warps, warp w owns Q rows [16w, 16w+16).
// ===========================================================================
#define FLASH_DYN_SMEM (3 * 65536 + 1024)

__global__ __launch_bounds__(256, 1)
void flash_attn(const __nv_bfloat16* __restrict__ q2,
                const __nv_bfloat16* __restrict__ k2,
                const __nv_bfloat16* __restrict__ vt,
                float* __restrict__ ctx)
{
    extern __shared__ char dyn[];
    __shared__ __align__(8) unsigned long long s_mbar[5]; // qfull,kfull,kempty,vfull,vempty

    const int tid = threadIdx.x, wid = tid >> 5, lane = tid & 31;
    const int qb = blockIdx.x, h = blockIdx.y;
    const float L2E = 1.44269504f;

    uint32_t base = (smem_u32(dyn) + 1023u) & ~1023u;
    uint32_t Qs = base, Ks = base + 65536, Vs = base + 131072;
    uint32_t mb = smem_u32(s_mbar);

    if (tid == 0) {
        MBARRIER_INIT(mb + 0, 1);   // qfull
        MBARRIER_INIT(mb + 8, 1);   // kfull
        MBARRIER_INIT(mb + 16, 8);  // kempty
        MBARRIER_INIT(mb + 24, 1);  // vfull
        MBARRIER_INIT(mb + 32, 8);  // vempty
    }
    __syncthreads();

    const char* Qg = (const char*)q2 + (size_t)h * SEQ * 2 * HD * 2 + (((size_t)qb * 4) << 14);
    const char* Kg = (const char*)k2 + (size_t)h * SEQ * 2 * HD * 2;
    const char* Vg = (const char*)vt + (size_t)h * HD * 2 * SEQ * 2;

    if (tid == 0) {
        MBARRIER_EXPECT_TX(mb + 0, 65536);
        bulk_g2s(Qs, Qg, 65536, mb + 0);
        MBARRIER_EXPECT_TX(mb + 8, 65536);
        bulk_g2s(Ks, Kg, 65536, mb + 8);
        MBARRIER_EXPECT_TX(mb + 24, 65536);
        bulk_g2s(Vs,         Vg,                      32768, mb + 24);
        bulk_g2s(Vs + 32768, Vg + ((size_t)32 << 14), 32768, mb + 24);
    }

    // A (Q/P) lane addressing
    const int r_a = wid * 16 + (lane & 15);
    const uint32_t a_row = (uint32_t)r_a * 128;
    const uint32_t a_sw  = ((uint32_t)(r_a & 7)) << 4;
    const uint32_t a_kh  = ((uint32_t)(lane >> 4)) * 16;
    // B (K/V^T) lane addressing
    const int r_b = (lane & 7) + ((lane >> 4) & 1) * 8;
    const uint32_t b_sw = ((uint32_t)(r_b & 7)) << 4;
    const uint32_t b_kh = ((uint32_t)((lane >> 3) & 1)) * 16;

    float oacc[16][4];
    #pragma unroll
    for (int i = 0; i < 16; i++)
        #pragma unroll
        for (int q = 0; q < 4; q++) oacc[i][q] = 0.f;
    float m0 = -1e30f, m1 = -1e30f, l0 = 0.f, l1 = 0.f;

    MBARRIER_WAIT_PARITY(mb + 0, 0);   // Q resident

    for (int j = 0; j < 16; j++) {
        const int ph = j & 1;
        float sacc[16][4];
        #pragma unroll
        for (int i = 0; i < 16; i++)
            #pragma unroll
            for (int q = 0; q < 4; q++) sacc[i][q] = 0.f;

        MBARRIER_WAIT_PARITY(mb + 8, ph);   // K(j) ready

        // ---- S = Q @ K^T (3 terms) ----
        #pragma unroll
        for (int t = 0; t < 3; t++) {
            uint32_t qtb = Qs + (t == 1 ? 2 : 0) * 16384;
            uint32_t ktb = Ks + (t == 2 ? 2 : 0) * 16384;
            #pragma unroll
            for (int kk = 0; kk < 8; kk++) {
                uint32_t a0, a1, a2, a3;
                ldsm_x4(qtb + (kk >> 2) * 16384 + a_row + (a_sw ^ (a_kh + (kk & 3) * 32)),
                        a0, a1, a2, a3);
                uint32_t kbb = ktb + (kk >> 2) * 16384;
                uint32_t kcol = b_sw ^ (b_kh + (kk & 3) * 32);
                #pragma unroll
                for (int u = 0; u < 8; u++) {
                    uint32_t b0, b1, b2, b3;
                    ldsm_x4(kbb + (uint32_t)(r_b + u * 16) * 128 + kcol, b0, b1, b2, b3);
                    mma_bf16(sacc[2 * u],     a0, a1, a2, a3, b0, b1);
                    mma_bf16(sacc[2 * u + 1], a0, a1, a2, a3, b2, b3);
                }
            }
        }

        // release K, prefetch K(j+1)
        if (lane == 0) MBARRIER_ARRIVE(mb + 16);
        if (tid == 0 && j < 15) {
            MBARRIER_WAIT_PARITY_RELAXED(mb + 16, ph);
            MBARRIER_EXPECT_TX(mb + 8, 65536);
            bulk_g2s(Ks, Kg + (((size_t)(j + 1) * 4) << 14), 65536, mb + 8);
        }

        // ---- online softmax (registers only) ----
        float rmax0 = -1e30f, rmax1 = -1e30f;
        #pragma unroll
        for (int i = 0; i < 16; i++) {
            rmax0 = fmaxf(rmax0, fmaxf(sacc[i][0], sacc[i][1]));
            rmax1 = fmaxf(rmax1, fmaxf(sacc[i][2], sacc[i][3]));
        }
        rmax0 = fmaxf(rmax0, __shfl_xor_sync(0xffffffffu, rmax0, 1));
        rmax0 = fmaxf(rmax0, __shfl_xor_sync(0xffffffffu, rmax0, 2));
        rmax1 = fmaxf(rmax1, __shfl_xor_sync(0xffffffffu, rmax1, 1));
        rmax1 = fmaxf(rmax1, __shfl_xor_sync(0xffffffffu, rmax1, 2));
        float mn0 = fmaxf(m0, rmax0), mn1 = fmaxf(m1, rmax1);
        float c0 = ex2f((m0 - mn0) * L2E), c1 = ex2f((m1 - mn1) * L2E);
        float rs0 = 0.f, rs1 = 0.f;
        #pragma unroll
        for (int i = 0; i < 16; i++) {
            float p0 = ex2f((sacc[i][0] - mn0) * L2E);
            float p1 = ex2f((sacc[i][1] - mn0) * L2E);
            float p2 = ex2f((sacc[i][2] - mn1) * L2E);
            float p3 = ex2f((sacc[i][3] - mn1) * L2E);
            sacc[i][0] = p0; sacc[i][1] = p1; sacc[i][2] = p2; sacc[i][3] = p3;
            rs0 += p0 + p1; rs1 += p2 + p3;
        }
        rs0 += __shfl_xor_sync(0xffffffffu, rs0, 1);
        rs0 += __shfl_xor_sync(0xffffffffu, rs0, 2);
        rs1 += __shfl_xor_sync(0xffffffffu, rs1, 1);
        rs1 += __shfl_xor_sync(0xffffffffu, rs1, 2);
        l0 = l0 * c0 + rs0;  l1 = l1 * c1 + rs1;
        m0 = mn0; m1 = mn1;
        #pragma unroll
        for (int i = 0; i < 16; i++) {
            oacc[i][0] *= c0; oacc[i][1] *= c0;
            oacc[i][2] *= c1; oacc[i][3] *= c1;
        }

        // ---- O += P @ V (3 terms: PhVh, PlVh, PhVl) ----
        MBARRIER_WAIT_PARITY(mb + 24, ph);   // V(j) ready
        #pragma unroll
        for (int u = 0; u < 8; u++) {        // k16 over the 128 seq cols
            // P frags (hi + residual lo) from sacc tiles 2u, 2u+1
            uint32_t phr[4], plr[4];
            #pragma unroll
            for (int q = 0; q < 4; q++) {
                float e0 = sacc[2 * u][q >= 2 ? (q - 2) + 2 : q];  // placeholder (fixed below)
                (void)e0;
            }
            {
                // a0: (r0, k0k1)=tile2u c0c1 ; a1: (r0+8)=tile2u c2c3 ;
                // a2: tile2u+1 c0c1 ; a3: tile2u+1 c2c3
                float e00 = sacc[2*u][0],   e01 = sacc[2*u][1];
                float e10 = sacc[2*u][2],   e11 = sacc[2*u][3];
                float e20 = sacc[2*u+1][0], e21 = sacc[2*u+1][1];
                float e30 = sacc[2*u+1][2], e31 = sacc[2*u+1][3];
                __nv_bfloat16 h00=__float2bfloat16(e00), h01=__float2bfloat16(e01);
                __nv_bfloat16 h10=__float2bfloat16(e10), h11=__float2bfloat16(e11);
                __nv_bfloat16 h20=__float2bfloat16(e20), h21=__float2bfloat16(e21);
                __nv_bfloat16 h30=__float2bfloat16(e30), h31=__float2bfloat16(e31);
                phr[0] = (uint32_t)__bfloat16_as_ushort(h00) | ((uint32_t)__bfloat16_as_ushort(h01) << 16);
                phr[1] = (uint32_t)__bfloat16_as_ushort(h10) | ((uint32_t)__bfloat16_as_ushort(h11) << 16);
                phr[2] = (uint32_t)__bfloat16_as_ushort(h20) | ((uint32_t)__bfloat16_as_ushort(h21) << 16);
                phr[3] = (uint32_t)__bfloat16_as_ushort(h30) | ((uint32_t)__bfloat16_as_ushort(h31) << 16);
                __nv_bfloat16 q00=__float2bfloat16(e00-__bfloat162float(h00));
                __nv_bfloat16 q01=__float2bfloat16(e01-__bfloat162float(h01));
                __nv_bfloat16 q10=__float2bfloat16(e10-__bfloat162float(h10));
                __nv_bfloat16 q11=__float2bfloat16(e11-__bfloat162float(h11));
                __nv_bfloat16 q20=__float2bfloat16(e20-__bfloat162float(h20));
                __nv_bfloat16 q21=__float2bfloat16(e21-__bfloat162float(h21));
                __nv_bfloat16 q30=__float2bfloat16(e30-__bfloat162float(h30));
                __nv_bfloat16 q31=__float2bfloat16(e31-__bfloat162float(h31));
                plr[0] = (uint32_t)__bfloat16_as_ushort(q00) | ((uint32_t)__bfloat16_as_ushort(q01) << 16);
                plr[1] = (uint32_t)__bfloat16_as_ushort(q10) | ((uint32_t)__bfloat16_as_ushort(q11) << 16);
                plr[2] = (uint32_t)__bfloat16_as_ushort(q20) | ((uint32_t)__bfloat16_as_ushort(q21) << 16);
                plr[3] = (uint32_t)__bfloat16_as_ushort(q30) | ((uint32_t)__bfloat16_as_ushort(q31) << 16);
            }
            uint32_t vhb = Vs + (u >> 2) * 16384;
            uint32_t vlb = vhb + 32768;
            uint32_t vcol = b_sw ^ (b_kh + (u & 3) * 32);
            #pragma unroll
            for (int v = 0; v < 8; v++) {    // n16 over d=128
                uint32_t roff = (uint32_t)(r_b + v * 16) * 128 + vcol;
                uint32_t b0, b1, b2, b3;
                ldsm_x4(vhb + roff, b0, b1, b2, b3);
                mma_bf16(oacc[2 * v],     phr[0], phr[1], phr[2], phr[3], b0, b1);
                mma_bf16(oacc[2 * v + 1], phr[0], phr[1], phr[2], phr[3], b2, b3);
                mma_bf16(oacc[2 * v],     plr[0], plr[1], plr[2], plr[3], b0, b1);
                mma_bf16(oacc[2 * v + 1], plr[0], plr[1], plr[2], plr[3], b2, b3);
                uint32_t c0r, c1r, c2r, c3r;
                ldsm_x4(vlb + roff, c0r, c1r, c2r, c3r);
                mma_bf16(oacc[2 * v],     phr[0], phr[1], phr[2], phr[3], c0r, c1r);
                mma_bf16(oacc[2 * v + 1], phr[0], phr[1], phr[2], phr[3], c2r, c3r);
            }
        }

        // release V, prefetch V(j+1)
        if (lane == 0) MBARRIER_ARRIVE(mb + 32);
        if (tid == 0 && j < 15) {
            MBARRIER_WAIT_PARITY_RELAXED(mb + 32, ph);
            MBARRIER_EXPECT_TX(mb + 24, 65536);
            bulk_g2s(Vs,         Vg + (((size_t)(2 * (j + 1))) << 14),      32768, mb + 24);
            bulk_g2s(Vs + 32768, Vg + (((size_t)(32 + 2 * (j + 1))) << 14), 32768, mb + 24);
        }
    }

    // ---- epilogue: O / l -> ctx[s, h*128 + d] fp32 ----
    float i0 = 1.0f / l0, i1 = 1.0f / l1;
    int srow = qb * 128 + wid * 16 + (lane >> 2);
    float* C0 = ctx + (size_t)srow * DMODEL + h * HD;
    #pragma unroll
    for (int nt = 0; nt < 16; nt++) {
        int cc = nt * 8 + (lane & 3) * 2;
        float2 v0 = { oacc[nt][0] * i0, oacc[nt][1] * i0 };
        float2 v1 = { oacc[nt][2] * i1, oacc[nt][3] * i1 };
        *(float2*)(C0 + cc)               = v0;
        *(float2*)(C0 + 8 * DMODEL + cc)  = v1;
    }
}

// ===========================================================================
extern "C" void kernel_launch(void* const* d_in, const int* in_sizes, int n_in,
                              void* d_out, int out_size)
{
    const float* hidden = (const float*)d_in[0];   // [2048, 4096]
    const float* wqkv   = (const float*)d_in[1];   // [4096, 12288]
    const float* wo     = (const float*)d_in[2];   // [4096, 4096]
    float* out = (float*)d_out;                    // [2048, 4096]

    float *qkv, *ctx;
    __nv_bfloat16 *x2, *w1, *w2, *q2, *k2, *vt, *c2;
    cudaGetSymbolAddress((void**)&qkv, g_qkv);
    cudaGetSymbolAddress((void**)&ctx, g_ctx);
    cudaGetSymbolAddress((void**)&x2, g_x2);
    cudaGetSymbolAddress((void**)&w1, g_w1);
    cudaGetSymbolAddress((void**)&w2, g_w2);
    cudaGetSymbolAddress((void**)&q2, g_q2);
    cudaGetSymbolAddress((void**)&k2, g_k2);
    cudaGetSymbolAddress((void**)&vt, g_vt);
    cudaGetSymbolAddress((void**)&c2, g_c2);

    cudaFuncSetAttribute(gemm_mma, cudaFuncAttributeMaxDynamicSharedMemorySize, GEMM_DYN_SMEM);
    cudaFuncSetAttribute(flash_attn, cudaFuncAttributeMaxDynamicSharedMemorySize, FLASH_DYN_SMEM);

    // ---- operand conversion ----
    split_tiles_g<<<dim3((2048 * 512 + 255) / 256, 1), 256>>>(
        hidden, x2, 2048, 4096, 4096, 0, 0);
    transpose_split_g<<<dim3(12288 / 32, 4096 / 32, 1), dim3(32, 8)>>>(
        wqkv, w1, 4096, 12288, 12288, 0, 0);
    transpose_split_g<<<dim3(4096 / 32, 4096 / 32, 1), dim3(32, 8)>>>(
        wo, w2, 4096, 4096, 4096, 0, 0);

    // ---- QKV GEMM ----
    gemm_mma<<<dim3(8, 96, 1), 256, GEMM_DYN_SMEM>>>(
        x2, w1, qkv, 64, 12288, 0, 0, 0, 1.0f);

    // ---- RoPE + Q/K split (scale folded into Q) ----
    build_rope_table<<<(SEQ * (HD / 2) + 255) / 256, 256>>>();
    rope_split<<<(SEQ * NH * 16 + 255) / 256, 256>>>(qkv, q2, k2);

    // ---- V^T split per head ----
    transpose_split_g<<<dim3(128 / 32, 2048 / 32, NH), dim3(32, 8)>>>(
        qkv + 2 * DMODEL, vt, 2048, 128, 3 * DMODEL,
        /*izs=*/HD, /*ozs=*/(long long)HD * 2 * SEQ);

    // ---- fused flash attention ----
    flash_attn<<<dim3(16, NH), 256, FLASH_DYN_SMEM>>>(q2, k2, vt, ctx);

    // ---- ctx split ----
    split_tiles_g<<<dim3((2048 * 512 + 255) / 256, 1), 256>>>(
        ctx, c2, 2048, 4096, 4096, 0, 0);

    // ---- out = ctx @ Wo ----
    gemm_mma<<<dim3(8, 32, 1), 256, GEMM_DYN_SMEM>>>(
        c2, w2, out, 64, 4096, 0, 0, 0, 1.0f);
}

// round 11
// speedup vs baseline: 3.8005x; 1.0598x over previous
#include <cuda_runtime.h>
#include <cuda_bf16.h>
#include <math.h>
#include <stdint.h>

#define SEQ 2048
#define DMODEL 4096
#define NH 32
#define HD 128

// ===========================================================================
// PTX helpers (sm_103-safe subset)
// ===========================================================================
__device__ __forceinline__ uint32_t smem_u32(const void* p) {
    uint32_t a;
    asm("{ .reg .u64 t; cvta.to.shared.u64 t, %1; cvt.u32.u64 %0, t; }" : "=r"(a) : "l"(p));
    return a;
}
#define MBARRIER_INIT(addr, cnt) \
    asm volatile("mbarrier.init.shared.b64 [%0], %1;" :: "r"((uint32_t)(addr)), "r"((uint32_t)(cnt)) : "memory")
#define MBARRIER_EXPECT_TX(addr, bytes) \
    asm volatile("mbarrier.arrive.expect_tx.shared.b64 _, [%0], %1;" :: "r"((uint32_t)(addr)), "r"((uint32_t)(bytes)) : "memory")
#define MBARRIER_ARRIVE(addr) \
    asm volatile("mbarrier.arrive.shared.b64 _, [%0];" :: "r"((uint32_t)(addr)) : "memory")

#define MBARRIER_WAIT_PARITY(mbar_smem_addr, phase_parity) do { \
    uint32_t _mbar = (uint32_t)(mbar_smem_addr); \
    uint32_t _parity = (uint32_t)(phase_parity); \
    uint32_t _done; \
    asm volatile("{\n\t.reg .pred p;\n\t" \
        "mbarrier.try_wait.parity.acquire.cta.shared::cta.b64 p, [%1], %2;\n\t" \
        "selp.b32 %0, 1, 0, p;\n\t}" : "=r"(_done) : "r"(_mbar), "r"(_parity) : "memory"); \
    if (!_done) { \
        asm volatile("{\n\t.reg .pred P1;\n\t" \
            "WAIT_LOOP_%=:\n\t" \
            "mbarrier.try_wait.parity.acquire.cta.shared::cta.b64 P1, [%0], %1, 0x989680;\n\t" \
            "@P1 bra.uni WAIT_DONE_%=;\n\t" \
            "bra.uni WAIT_LOOP_%=;\n\t" \
            "WAIT_DONE_%=:\n\t}" :: "r"(_mbar), "r"(_parity) : "memory"); \
    } \
} while(0)

#define MBARRIER_WAIT_PARITY_RELAXED(mbar_smem_addr, phase_parity) do { \
    uint32_t _mbar = (uint32_t)(mbar_smem_addr); \
    uint32_t _parity = (uint32_t)(phase_parity); \
    uint32_t _done; \
    asm volatile("{\n\t.reg .pred p;\n\t" \
        "mbarrier.try_wait.parity.relaxed.cta.shared::cta.b64 p, [%1], %2, 0x989680;\n\t" \
        "selp.b32 %0, 1, 0, p;\n\t}" : "=r"(_done) : "r"(_mbar), "r"(_parity) : "memory"); \
    if (!_done) { \
        asm volatile("{\n\t.reg .pred P1;\n\t" \
            "WAIT_LOOP_%=:\n\t" \
            "mbarrier.try_wait.parity.relaxed.cta.shared::cta.b64 P1, [%0], %1, 0x989680;\n\t" \
            "@P1 bra.uni WAIT_DONE_%=;\n\t" \
            "bra.uni WAIT_LOOP_%=;\n\t" \
            "WAIT_DONE_%=:\n\t}" :: "r"(_mbar), "r"(_parity) : "memory"); \
    } \
} while(0)

__device__ __forceinline__ void bulk_g2s(uint32_t dst, const void* src,
                                         uint32_t bytes, uint32_t mbar) {
    asm volatile(
        "cp.async.bulk.shared::cluster.global.mbarrier::complete_tx::bytes [%0], [%1], %2, [%3];"
        :: "r"(dst), "l"(src), "r"(bytes), "r"(mbar) : "memory");
}

__device__ __forceinline__ void ldsm_x4(uint32_t addr, uint32_t& r0, uint32_t& r1,
                                        uint32_t& r2, uint32_t& r3) {
    asm volatile("ldmatrix.sync.aligned.m8n8.x4.shared.b16 {%0,%1,%2,%3}, [%4];"
        : "=r"(r0), "=r"(r1), "=r"(r2), "=r"(r3) : "r"(addr));
}

__device__ __forceinline__ void mma_bf16(float* c, uint32_t a0, uint32_t a1,
                                         uint32_t a2, uint32_t a3,
                                         uint32_t b0, uint32_t b1) {
    asm volatile(
        "mma.sync.aligned.m16n8k16.row.col.f32.bf16.bf16.f32 "
        "{%0,%1,%2,%3}, {%4,%5,%6,%7}, {%8,%9}, {%0,%1,%2,%3};"
        : "+f"(c[0]), "+f"(c[1]), "+f"(c[2]), "+f"(c[3])
        : "r"(a0), "r"(a1), "r"(a2), "r"(a3), "r"(b0), "r"(b1));
}

__device__ __forceinline__ float ex2f(float x) {
    float r;
    asm("ex2.approx.f32 %0, %1;" : "=f"(r) : "f"(x));
    return r;
}

// ===========================================================================
// Scratch (static device globals; no allocations anywhere)
// ===========================================================================
__device__ float g_qkv[(size_t)SEQ * 3 * DMODEL];
__device__ float g_ctx[(size_t)SEQ * DMODEL];
__device__ __align__(128) __nv_bfloat16 g_x2[(size_t)SEQ * 2 * DMODEL];
__device__ __align__(128) __nv_bfloat16 g_w1[(size_t)3 * DMODEL * 2 * DMODEL];
__device__ __align__(128) __nv_bfloat16 g_w2[(size_t)DMODEL * 2 * DMODEL];
__device__ __align__(128) __nv_bfloat16 g_q2[(size_t)NH * SEQ * 2 * HD];
__device__ __align__(128) __nv_bfloat16 g_k2[(size_t)NH * SEQ * 2 * HD];
__device__ __align__(128) __nv_bfloat16 g_vt[(size_t)NH * HD * 2 * SEQ];
__device__ __align__(128) __nv_bfloat16 g_c2[(size_t)SEQ * 2 * DMODEL];
__device__ float g_cos[SEQ * (HD / 2)];
__device__ float g_sin[SEQ * (HD / 2)];

// ===========================================================================
// Tiled/swizzled gmem layout: 128x64-bf16 tiles (16KB, SW128-swizzled)
// ===========================================================================
__device__ __forceinline__ size_t granule_off(int r, int k8, int ktiles) {
    int kt = k8 >> 3;
    uint32_t b = (uint32_t)((r & 127) * 128)
               + (((uint32_t)(k8 & 7) << 4) ^ ((uint32_t)(r & 7) << 4));
    return ((size_t)((r >> 7) * ktiles + kt) << 14) + b;
}

__device__ __forceinline__ void split8(const float* v, uint4& hi, uint4& lo) {
    uint32_t hw[4], lw[4];
    #pragma unroll
    for (int j = 0; j < 4; j++) {
        __nv_bfloat16 h0 = __float2bfloat16(v[2 * j]);
        __nv_bfloat16 h1 = __float2bfloat16(v[2 * j + 1]);
        __nv_bfloat16 l0 = __float2bfloat16(v[2 * j]     - __bfloat162float(h0));
        __nv_bfloat16 l1 = __float2bfloat16(v[2 * j + 1] - __bfloat162float(h1));
        hw[j] = (uint32_t)__bfloat16_as_ushort(h0) | ((uint32_t)__bfloat16_as_ushort(h1) << 16);
        lw[j] = (uint32_t)__bfloat16_as_ushort(l0) | ((uint32_t)__bfloat16_as_ushort(l1) << 16);
    }
    hi = make_uint4(hw[0], hw[1], hw[2], hw[3]);
    lo = make_uint4(lw[0], lw[1], lw[2], lw[3]);
}

__global__ __launch_bounds__(256)
void split_tiles_g(const float* __restrict__ in, __nv_bfloat16* __restrict__ out,
                   int R, int K, int ldin, long long izs, long long ozs)
{
    int z = blockIdx.y;
    long long idx = (long long)blockIdx.x * 256 + threadIdx.x;
    int kg = K / 8;
    long long tot = (long long)R * kg;
    if (idx >= tot) return;
    int r  = (int)(idx / kg);
    int k8 = (int)(idx - (long long)r * kg);
    const float* p = in + (long long)z * izs + (long long)r * ldin + k8 * 8;
    float v[8];
    float4 a = *(const float4*)p, b = *(const float4*)(p + 4);
    v[0]=a.x; v[1]=a.y; v[2]=a.z; v[3]=a.w; v[4]=b.x; v[5]=b.y; v[6]=b.z; v[7]=b.w;
    uint4 hi, lo; split8(v, hi, lo);
    char* o = (char*)(out + (long long)z * ozs);
    int ktiles = 2 * (K / 64);
    *(uint4*)(o + granule_off(r, k8, ktiles))          = hi;
    *(uint4*)(o + granule_off(r, k8 + K / 8, ktiles))  = lo;
}

__global__ __launch_bounds__(256)
void transpose_split_g(const float* __restrict__ in, __nv_bfloat16* __restrict__ out,
                       int K, int N, int ldin, long long izs, long long ozs)
{
    __shared__ float t[32][33];
    int z = blockIdx.z;
    const float* inz = in + (long long)z * izs;
    char* outz = (char*)(out + (long long)z * ozs);
    int n0 = blockIdx.x * 32, k0 = blockIdx.y * 32;
    int x = threadIdx.x, y = threadIdx.y;   // 32 x 8
    #pragma unroll
    for (int r = 0; r < 32; r += 8)
        t[y + r][x] = inz[(long long)(k0 + y + r) * ldin + n0 + x];
    __syncthreads();
    int tt = y * 32 + x;
    if (tt < 128) {
        int nn = tt >> 2, g = tt & 3;
        float v[8];
        #pragma unroll
        for (int j = 0; j < 8; j++) v[j] = t[g * 8 + j][nn];
        uint4 hi, lo; split8(v, hi, lo);
        int ktiles = 2 * (K / 64);
        int n = n0 + nn, k8 = (k0 >> 3) + g;
        *(uint4*)(outz + granule_off(n, k8, ktiles))         = hi;
        *(uint4*)(outz + granule_off(n, k8 + K / 8, ktiles)) = lo;
    }
}

// ===========================================================================
// mma.sync bf16 GEMM (3-term chunks over 2-term storage), 4-stage pipeline
// ===========================================================================
#define GST 4
#define STAGE_BYTES 49152
#define GEMM_DYN_SMEM (GST * STAGE_BYTES + 1024)

__global__ __launch_bounds__(256, 1)
void gemm_mma(const __nv_bfloat16* __restrict__ A, const __nv_bfloat16* __restrict__ B,
              float* __restrict__ C, int nk0, int ldc,
              long long Az, long long Bz, long long Cz, float alpha)
{
    extern __shared__ char dyn[];
    __shared__ __align__(8) unsigned long long s_mbar[2 * GST];

    const int tid  = threadIdx.x;
    const int wid  = tid >> 5;
    const int lane = tid & 31;
    const int wm = wid >> 1, wn = wid & 1;
    const int mt2 = blockIdx.x, ntb = blockIdx.y, z = blockIdx.z;
    const int nk = 3 * nk0;

    uint32_t stages = (smem_u32(dyn) + 1023u) & ~1023u;
    uint32_t mb = smem_u32(s_mbar);

    if (tid == 0) {
        #pragma unroll
        for (int i = 0; i < GST; i++)  MBARRIER_INIT(mb + i * 8, 1);
        #pragma unroll
        for (int i = GST; i < 2 * GST; i++) MBARRIER_INIT(mb + i * 8, 8);
    }
    __syncthreads();

    const char* Ab = (const char*)A + (size_t)z * Az * 2 + (((size_t)(2 * mt2) * (2 * nk0)) << 14);
    const char* Bb = (const char*)B + (size_t)z * Bz * 2 + (((size_t)ntb * (2 * nk0)) << 14);
    const size_t Astride = ((size_t)(2 * nk0) << 14);

    if (tid == 0) {
        for (int c = 0; c < GST - 1 && c < nk; c++) {
            int t = c / nk0, k = c % nk0;
            size_t ao = ((size_t)((t == 1 ? nk0 : 0) + k)) << 14;
            size_t bo = ((size_t)((t == 2 ? nk0 : 0) + k)) << 14;
            uint32_t st = stages + c * STAGE_BYTES;
            MBARRIER_EXPECT_TX(mb + c * 8, STAGE_BYTES);
            bulk_g2s(st,         Ab + ao,           16384, mb + c * 8);
            bulk_g2s(st + 16384, Ab + Astride + ao, 16384, mb + c * 8);
            bulk_g2s(st + 32768, Bb + bo,           16384, mb + c * 8);
        }
    }

    const int r_a = wm * 64 + (lane & 15);
    const uint32_t a_rowoff = ((uint32_t)(r_a >> 7) << 14) + (uint32_t)(r_a & 127) * 128;
    const uint32_t a_sw = (uint32_t)(r_a & 7) << 4;
    const uint32_t cbA  = (uint32_t)(lane >> 4) * 16;

    const int r_b = wn * 64 + (lane & 7) + ((lane >> 4) & 1) * 8;
    const uint32_t b_rowoff = 32768u + (uint32_t)r_b * 128;
    const uint32_t b_sw = (uint32_t)(r_b & 7) << 4;
    const uint32_t cbB  = (uint32_t)((lane >> 3) & 1) * 16;

    float acc[4][8][4];
    #pragma unroll
    for (int i = 0; i < 4; i++)
        #pragma unroll
        for (int j = 0; j < 8; j++)
            #pragma unroll
            for (int q = 0; q < 4; q++) acc[i][j][q] = 0.f;

    for (int c = 0; c < nk; c++) {
        if (tid == 0) {
            int jc = c + GST - 1;
            if (jc < nk) {
                int t = jc / nk0, k = jc % nk0;
                size_t ao = ((size_t)((t == 1 ? nk0 : 0) + k)) << 14;
                size_t bo = ((size_t)((t == 2 ? nk0 : 0) + k)) << 14;
                int s2 = jc % GST;
                if (jc >= GST)
                    MBARRIER_WAIT_PARITY_RELAXED(mb + (GST + s2) * 8, ((jc / GST) - 1) & 1);
                uint32_t st = stages + s2 * STAGE_BYTES;
                MBARRIER_EXPECT_TX(mb + s2 * 8, STAGE_BYTES);
                bulk_g2s(st,         Ab + ao,           16384, mb + s2 * 8);
                bulk_g2s(st + 16384, Ab + Astride + ao, 16384, mb + s2 * 8);
                bulk_g2s(st + 32768, Bb + bo,           16384, mb + s2 * 8);
            }
        }

        int s = c % GST;
        MBARRIER_WAIT_PARITY(mb + s * 8, (c / GST) & 1);
        uint32_t st = stages + s * STAGE_BYTES;
        uint32_t abase = st + a_rowoff;
        uint32_t bbase = st + b_rowoff;

        #pragma unroll
        for (int kk = 0; kk < 4; kk++) {
            uint32_t a[4][4];
            uint32_t acol = a_sw ^ (cbA + kk * 32);
            #pragma unroll
            for (int mt = 0; mt < 4; mt++)
                ldsm_x4(abase + mt * 2048 + acol, a[mt][0], a[mt][1], a[mt][2], a[mt][3]);

            uint32_t b[8][2];
            uint32_t bcol = b_sw ^ (cbB + kk * 32);
            #pragma unroll
            for (int u = 0; u < 4; u++) {
                uint32_t r0, r1, r2, r3;
                ldsm_x4(bbase + u * 2048 + bcol, r0, r1, r2, r3);
                b[2 * u][0] = r0; b[2 * u][1] = r1;
                b[2 * u + 1][0] = r2; b[2 * u + 1][1] = r3;
            }

            #pragma unroll
            for (int mt = 0; mt < 4; mt++)
                #pragma unroll
                for (int nt = 0; nt < 8; nt++)
                    mma_bf16(acc[mt][nt], a[mt][0], a[mt][1], a[mt][2], a[mt][3],
                             b[nt][0], b[nt][1]);
        }

        if (lane == 0) MBARRIER_ARRIVE(mb + (GST + s) * 8);
    }

    float* Cb = C + (size_t)z * Cz;
    const int row0 = mt2 * 256 + wm * 64;
    const int col0 = ntb * 128 + wn * 64;
    #pragma unroll
    for (int mt = 0; mt < 4; mt++) {
        int r = row0 + mt * 16 + (lane >> 2);
        #pragma unroll
        for (int nt = 0; nt < 8; nt++) {
            int cc = col0 + nt * 8 + (lane & 3) * 2;
            float2 v0 = { acc[mt][nt][0] * alpha, acc[mt][nt][1] * alpha };
            float2 v1 = { acc[mt][nt][2] * alpha, acc[mt][nt][3] * alpha };
            *(float2*)(Cb + (size_t)r * ldc + cc)       = v0;
            *(float2*)(Cb + (size_t)(r + 8) * ldc + cc) = v1;
        }
    }
}

// ===========================================================================
// RoPE table + fused rope->split. Q gets 1/sqrt(HD) folded in.
// ===========================================================================
__global__ void build_rope_table()
{
    int idx = blockIdx.x * blockDim.x + threadIdx.x;
    if (idx >= SEQ * (HD / 2)) return;
    int i = idx % (HD / 2);
    int s = idx / (HD / 2);
    double freq_d = pow(10000.0, -(double)(2 * i) / (double)HD);
    float freq  = (float)freq_d;
    float angle = (float)s * freq;
    g_cos[idx] = (float)cos((double)angle);
    g_sin[idx] = (float)sin((double)angle);
}

__global__ __launch_bounds__(256)
void rope_split(const float* __restrict__ qkv,
                __nv_bfloat16* __restrict__ q2, __nv_bfloat16* __restrict__ k2)
{
    const float SCALE = 0.08838834764831845f;
    int idx = blockIdx.x * 256 + threadIdx.x;        // (s, h, j)
    if (idx >= SEQ * NH * 16) return;
    int j = idx & 15;
    int h = (idx >> 4) & 31;
    int s = idx >> 9;

    const float* qp = qkv + (long long)s * (3 * DMODEL) + h * HD + j * 8;
    float q[8], k[8];
    {
        float4 a = *(const float4*)qp, b = *(const float4*)(qp + 4);
        q[0]=a.x; q[1]=a.y; q[2]=a.z; q[3]=a.w; q[4]=b.x; q[5]=b.y; q[6]=b.z; q[7]=b.w;
        float4 c = *(const float4*)(qp + DMODEL), d = *(const float4*)(qp + DMODEL + 4);
        k[0]=c.x; k[1]=c.y; k[2]=c.z; k[3]=c.w; k[4]=d.x; k[5]=d.y; k[6]=d.z; k[7]=d.w;
    }
    #pragma unroll
    for (int p = 0; p < 4; p++) {
        int i = j * 4 + p;
        float c  = g_cos[s * 64 + i];
        float sn = g_sin[s * 64 + i];
        float q0 = q[2*p], q1 = q[2*p+1];
        q[2*p]   = (q0 * c - q1 * sn) * SCALE;
        q[2*p+1] = (q0 * sn + q1 * c) * SCALE;
        float k0 = k[2*p], k1 = k[2*p+1];
        k[2*p]   = k0 * c - k1 * sn;
        k[2*p+1] = k0 * sn + k1 * c;
    }
    uint4 qhi, qlo, khi, klo;
    split8(q, qhi, qlo);
    split8(k, khi, klo);
    char* qo = (char*)(q2 + (long long)h * SEQ * 2 * HD);
    char* ko = (char*)(k2 + (long long)h * SEQ * 2 * HD);
    *(uint4*)(qo + granule_off(s, j, 4))      = qhi;
    *(uint4*)(qo + granule_off(s, j + 16, 4)) = qlo;
    *(uint4*)(ko + granule_off(s, j, 4))      = khi;
    *(uint4*)(ko + granule_off(s, j + 16, 4)) = klo;
}

// ===========================================================================
// Flash attention v2: one CTA = (128 Q rows, head). BN=64 K/V blocks,
// both double-buffered; 32 j-iterations. S, softmax, P-resplit, O all in regs.
// smem: Q 64K | K0 32K | K1 32K | V0 32K | V1 32K  (192 KB)
// K slot layout: [hi_d0 8K][hi_d1 8K][lo_d0 8K][lo_d1 8K] (64 rows each)
// V slot layout: [hi 16K][lo 16K] (128 d-rows x 64 s-cols each)
// ===========================================================================
#define FLASH_DYN_SMEM (3 * 65536 + 1024)

__global__ __launch_bounds__(256, 1)
void flash_attn(const __nv_bfloat16* __restrict__ q2,
                const __nv_bfloat16* __restrict__ k2,
                const __nv_bfloat16* __restrict__ vt,
                float* __restrict__ ctx)
{
    extern __shared__ char dyn[];
    __shared__ __align__(8) unsigned long long s_mbar[9];
    // 0: qfull | 1,2: kfull[2] | 3,4: kempty[2] | 5,6: vfull[2] | 7,8: vempty[2]

    const int tid = threadIdx.x, wid = tid >> 5, lane = tid & 31;
    const int qb = blockIdx.x, h = blockIdx.y;
    const float L2E = 1.44269504f;

    uint32_t base = (smem_u32(dyn) + 1023u) & ~1023u;
    uint32_t Qs = base;
    uint32_t Kslot[2] = { base + 65536, base + 98304 };
    uint32_t Vslot[2] = { base + 131072, base + 163840 };
    uint32_t mb = smem_u32(s_mbar);

    if (tid == 0) {
        MBARRIER_INIT(mb + 0, 1);
        #pragma unroll
        for (int i = 1; i <= 2; i++) MBARRIER_INIT(mb + i * 8, 1);   // kfull
        #pragma unroll
        for (int i = 3; i <= 4; i++) MBARRIER_INIT(mb + i * 8, 8);   // kempty
        #pragma unroll
        for (int i = 5; i <= 6; i++) MBARRIER_INIT(mb + i * 8, 1);   // vfull
        #pragma unroll
        for (int i = 7; i <= 8; i++) MBARRIER_INIT(mb + i * 8, 8);   // vempty
    }
    __syncthreads();

    const char* Qg = (const char*)q2 + (size_t)h * SEQ * 2 * HD * 2 + (((size_t)qb * 4) << 14);
    const char* Kg = (const char*)k2 + (size_t)h * SEQ * 2 * HD * 2;
    const char* Vg = (const char*)vt + (size_t)h * HD * 2 * SEQ * 2;

    // load K block j (64 rows) into slot: 4 x 8KB (hi_d0, hi_d1, lo_d0, lo_d1)
    auto load_k = [&](int j, int s) {
        size_t tr = ((size_t)(j >> 1) * 4) << 14;
        size_t half = (size_t)(j & 1) * 8192;
        MBARRIER_EXPECT_TX(mb + (1 + s) * 8, 32768);
        #pragma unroll
        for (int kt = 0; kt < 4; kt++)
            bulk_g2s(Kslot[s] + kt * 8192, Kg + tr + ((size_t)kt << 14) + half,
                     8192, mb + (1 + s) * 8);
    };
    // load V block j: hi tile j, lo tile 32+j
    auto load_v = [&](int j, int s) {
        MBARRIER_EXPECT_TX(mb + (5 + s) * 8, 32768);
        bulk_g2s(Vslot[s],         Vg + ((size_t)j << 14),        16384, mb + (5 + s) * 8);
        bulk_g2s(Vslot[s] + 16384, Vg + ((size_t)(32 + j) << 14), 16384, mb + (5 + s) * 8);
    };

    if (tid == 0) {
        MBARRIER_EXPECT_TX(mb + 0, 65536);
        bulk_g2s(Qs, Qg, 65536, mb + 0);
        load_k(0, 0); load_k(1, 1);
        load_v(0, 0); load_v(1, 1);
    }

    // A (Q/P) lane addressing
    const int r_a = wid * 16 + (lane & 15);
    const uint32_t a_row = (uint32_t)r_a * 128;
    const uint32_t a_sw  = ((uint32_t)(r_a & 7)) << 4;
    const uint32_t a_kh  = ((uint32_t)(lane >> 4)) * 16;
    // B (K/V^T) lane addressing
    const int r_b = (lane & 7) + ((lane >> 4) & 1) * 8;
    const uint32_t b_sw = ((uint32_t)(r_b & 7)) << 4;
    const uint32_t b_kh = ((uint32_t)((lane >> 3) & 1)) * 16;

    float oacc[16][4];
    #pragma unroll
    for (int i = 0; i < 16; i++)
        #pragma unroll
        for (int q = 0; q < 4; q++) oacc[i][q] = 0.f;
    float m0 = -1e30f, m1 = -1e30f, l0 = 0.f, l1 = 0.f;

    MBARRIER_WAIT_PARITY(mb + 0, 0);   // Q resident

    for (int j = 0; j < 32; j++) {
        const int s = j & 1;
        const int ph = (j >> 1) & 1;
        float sacc[8][4];
        #pragma unroll
        for (int i = 0; i < 8; i++)
            #pragma unroll
            for (int q = 0; q < 4; q++) sacc[i][q] = 0.f;

        MBARRIER_WAIT_PARITY(mb + (1 + s) * 8, ph);   // K(j) ready

        // ---- S(128x64) = Q @ K^T (3 terms) ----
        #pragma unroll
        for (int t = 0; t < 3; t++) {
            uint32_t qtb = Qs + (t == 1 ? 32768 : 0);
            uint32_t ktb = Kslot[s] + (t == 2 ? 16384 : 0);
            #pragma unroll
            for (int kk = 0; kk < 8; kk++) {
                uint32_t a0, a1, a2, a3;
                ldsm_x4(qtb + (kk >> 2) * 16384 + a_row + (a_sw ^ (a_kh + (kk & 3) * 32)),
                        a0, a1, a2, a3);
                uint32_t kbb = ktb + (kk >> 2) * 8192;
                uint32_t kcol = b_sw ^ (b_kh + (kk & 3) * 32);
                #pragma unroll
                for (int u = 0; u < 4; u++) {
                    uint32_t b0, b1, b2, b3;
                    ldsm_x4(kbb + (uint32_t)(r_b + u * 16) * 128 + kcol, b0, b1, b2, b3);
                    mma_bf16(sacc[2 * u],     a0, a1, a2, a3, b0, b1);
                    mma_bf16(sacc[2 * u + 1], a0, a1, a2, a3, b2, b3);
                }
            }
        }

        // release K(j); prefetch K(j+2)
        if (lane == 0) MBARRIER_ARRIVE(mb + (3 + s) * 8);
        if (tid == 0 && j + 2 < 32) {
            MBARRIER_WAIT_PARITY_RELAXED(mb + (3 + s) * 8, ph);
            load_k(j + 2, s);
        }

        // ---- online softmax ----
        float rmax0 = -1e30f, rmax1 = -1e30f;
        #pragma unroll
        for (int i = 0; i < 8; i++) {
            rmax0 = fmaxf(rmax0, fmaxf(sacc[i][0], sacc[i][1]));
            rmax1 = fmaxf(rmax1, fmaxf(sacc[i][2], sacc[i][3]));
        }
        rmax0 = fmaxf(rmax0, __shfl_xor_sync(0xffffffffu, rmax0, 1));
        rmax0 = fmaxf(rmax0, __shfl_xor_sync(0xffffffffu, rmax0, 2));
        rmax1 = fmaxf(rmax1, __shfl_xor_sync(0xffffffffu, rmax1, 1));
        rmax1 = fmaxf(rmax1, __shfl_xor_sync(0xffffffffu, rmax1, 2));
        float mn0 = fmaxf(m0, rmax0), mn1 = fmaxf(m1, rmax1);
        float c0 = ex2f((m0 - mn0) * L2E), c1 = ex2f((m1 - mn1) * L2E);
        float rs0 = 0.f, rs1 = 0.f;
        #pragma unroll
        for (int i = 0; i < 8; i++) {
            float p0 = ex2f((sacc[i][0] - mn0) * L2E);
            float p1 = ex2f((sacc[i][1] - mn0) * L2E);
            float p2 = ex2f((sacc[i][2] - mn1) * L2E);
            float p3 = ex2f((sacc[i][3] - mn1) * L2E);
            sacc[i][0] = p0; sacc[i][1] = p1; sacc[i][2] = p2; sacc[i][3] = p3;
            rs0 += p0 + p1; rs1 += p2 + p3;
        }
        rs0 += __shfl_xor_sync(0xffffffffu, rs0, 1);
        rs0 += __shfl_xor_sync(0xffffffffu, rs0, 2);
        rs1 += __shfl_xor_sync(0xffffffffu, rs1, 1);
        rs1 += __shfl_xor_sync(0xffffffffu, rs1, 2);
        l0 = l0 * c0 + rs0;  l1 = l1 * c1 + rs1;
        m0 = mn0; m1 = mn1;
        #pragma unroll
        for (int i = 0; i < 16; i++) {
            oacc[i][0] *= c0; oacc[i][1] *= c0;
            oacc[i][2] *= c1; oacc[i][3] *= c1;
        }

        // ---- O += P @ V (3 terms: PhVh, PlVh, PhVl) ----
        MBARRIER_WAIT_PARITY(mb + (5 + s) * 8, ph);   // V(j) ready
        #pragma unroll
        for (int u = 0; u < 4; u++) {        // k16 over the 64 seq cols
            uint32_t phr[4], plr[4];
            {
                float e00 = sacc[2*u][0],   e01 = sacc[2*u][1];
                float e10 = sacc[2*u][2],   e11 = sacc[2*u][3];
                float e20 = sacc[2*u+1][0], e21 = sacc[2*u+1][1];
                float e30 = sacc[2*u+1][2], e31 = sacc[2*u+1][3];
                __nv_bfloat16 h00=__float2bfloat16(e00), h01=__float2bfloat16(e01);
                __nv_bfloat16 h10=__float2bfloat16(e10), h11=__float2bfloat16(e11);
                __nv_bfloat16 h20=__float2bfloat16(e20), h21=__float2bfloat16(e21);
                __nv_bfloat16 h30=__float2bfloat16(e30), h31=__float2bfloat16(e31);
                phr[0] = (uint32_t)__bfloat16_as_ushort(h00) | ((uint32_t)__bfloat16_as_ushort(h01) << 16);
                phr[1] = (uint32_t)__bfloat16_as_ushort(h10) | ((uint32_t)__bfloat16_as_ushort(h11) << 16);
                phr[2] = (uint32_t)__bfloat16_as_ushort(h20) | ((uint32_t)__bfloat16_as_ushort(h21) << 16);
                phr[3] = (uint32_t)__bfloat16_as_ushort(h30) | ((uint32_t)__bfloat16_as_ushort(h31) << 16);
                __nv_bfloat16 q00=__float2bfloat16(e00-__bfloat162float(h00));
                __nv_bfloat16 q01=__float2bfloat16(e01-__bfloat162float(h01));
                __nv_bfloat16 q10=__float2bfloat16(e10-__bfloat162float(h10));
                __nv_bfloat16 q11=__float2bfloat16(e11-__bfloat162float(h11));
                __nv_bfloat16 q20=__float2bfloat16(e20-__bfloat162float(h20));
                __nv_bfloat16 q21=__float2bfloat16(e21-__bfloat162float(h21));
                __nv_bfloat16 q30=__float2bfloat16(e30-__bfloat162float(h30));
                __nv_bfloat16 q31=__float2bfloat16(e31-__bfloat162float(h31));
                plr[0] = (uint32_t)__bfloat16_as_ushort(q00) | ((uint32_t)__bfloat16_as_ushort(q01) << 16);
                plr[1] = (uint32_t)__bfloat16_as_ushort(q10) | ((uint32_t)__bfloat16_as_ushort(q11) << 16);
                plr[2] = (uint32_t)__bfloat16_as_ushort(q20) | ((uint32_t)__bfloat16_as_ushort(q21) << 16);
                plr[3] = (uint32_t)__bfloat16_as_ushort(q30) | ((uint32_t)__bfloat16_as_ushort(q31) << 16);
            }
            uint32_t vhb = Vslot[s];
            uint32_t vlb = vhb + 16384;
            uint32_t vcol = b_sw ^ (b_kh + u * 32);
            #pragma unroll
            for (int v = 0; v < 8; v++) {    // n16 over d=128
                uint32_t roff = (uint32_t)(r_b + v * 16) * 128 + vcol;
                uint32_t b0, b1, b2, b3;
                ldsm_x4(vhb + roff, b0, b1, b2, b3);
                mma_bf16(oacc[2 * v],     phr[0], phr[1], phr[2], phr[3], b0, b1);
                mma_bf16(oacc[2 * v + 1], phr[0], phr[1], phr[2], phr[3], b2, b3);
                mma_bf16(oacc[2 * v],     plr[0], plr[1], plr[2], plr[3], b0, b1);
                mma_bf16(oacc[2 * v + 1], plr[0], plr[1], plr[2], plr[3], b2, b3);
                uint32_t c0r, c1r, c2r, c3r;
                ldsm_x4(vlb + roff, c0r, c1r, c2r, c3r);
                mma_bf16(oacc[2 * v],     phr[0], phr[1], phr[2], phr[3], c0r, c1r);
                mma_bf16(oacc[2 * v + 1], phr[0], phr[1], phr[2], phr[3], c2r, c3r);
            }
        }

        // release V(j); prefetch V(j+2)
        if (lane == 0) MBARRIER_ARRIVE(mb + (7 + s) * 8);
        if (tid == 0 && j + 2 < 32) {
            MBARRIER_WAIT_PARITY_RELAXED(mb + (7 + s) * 8, ph);
            load_v(j + 2, s);
        }
    }

    // ---- epilogue: O / l -> ctx[s, h*128 + d] fp32 ----
    float i0 = 1.0f / l0, i1 = 1.0f / l1;
    int srow = qb * 128 + wid * 16 + (lane >> 2);
    float* C0 = ctx + (size_t)srow * DMODEL + h * HD;
    #pragma unroll
    for (int nt = 0; nt < 16; nt++) {
        int cc = nt * 8 + (lane & 3) * 2;
        float2 v0 = { oacc[nt][0] * i0, oacc[nt][1] * i0 };
        float2 v1 = { oacc[nt][2] * i1, oacc[nt][3] * i1 };
        *(float2*)(C0 + cc)               = v0;
        *(float2*)(C0 + 8 * DMODEL + cc)  = v1;
    }
}

// ===========================================================================
extern "C" void kernel_launch(void* const* d_in, const int* in_sizes, int n_in,
                              void* d_out, int out_size)
{
    const float* hidden = (const float*)d_in[0];   // [2048, 4096]
    const float* wqkv   = (const float*)d_in[1];   // [4096, 12288]
    const float* wo     = (const float*)d_in[2];   // [4096, 4096]
    float* out = (float*)d_out;                    // [2048, 4096]

    float *qkv, *ctx;
    __nv_bfloat16 *x2, *w1, *w2, *q2, *k2, *vt, *c2;
    cudaGetSymbolAddress((void**)&qkv, g_qkv);
    cudaGetSymbolAddress((void**)&ctx, g_ctx);
    cudaGetSymbolAddress((void**)&x2, g_x2);
    cudaGetSymbolAddress((void**)&w1, g_w1);
    cudaGetSymbolAddress((void**)&w2, g_w2);
    cudaGetSymbolAddress((void**)&q2, g_q2);
    cudaGetSymbolAddress((void**)&k2, g_k2);
    cudaGetSymbolAddress((void**)&vt, g_vt);
    cudaGetSymbolAddress((void**)&c2, g_c2);

    cudaFuncSetAttribute(gemm_mma, cudaFuncAttributeMaxDynamicSharedMemorySize, GEMM_DYN_SMEM);
    cudaFuncSetAttribute(flash_attn, cudaFuncAttributeMaxDynamicSharedMemorySize, FLASH_DYN_SMEM);

    // ---- operand conversion ----
    split_tiles_g<<<dim3((2048 * 512 + 255) / 256, 1), 256>>>(
        hidden, x2, 2048, 4096, 4096, 0, 0);
    transpose_split_g<<<dim3(12288 / 32, 4096 / 32, 1), dim3(32, 8)>>>(
        wqkv, w1, 4096, 12288, 12288, 0, 0);
    transpose_split_g<<<dim3(4096 / 32, 4096 / 32, 1), dim3(32, 8)>>>(
        wo, w2, 4096, 4096, 4096, 0, 0);

    // ---- QKV GEMM ----
    gemm_mma<<<dim3(8, 96, 1), 256, GEMM_DYN_SMEM>>>(
        x2, w1, qkv, 64, 12288, 0, 0, 0, 1.0f);

    // ---- RoPE + Q/K split (scale folded into Q) ----
    build_rope_table<<<(SEQ * (HD / 2) + 255) / 256, 256>>>();
    rope_split<<<(SEQ * NH * 16 + 255) / 256, 256>>>(qkv, q2, k2);

    // ---- V^T split per head ----
    transpose_split_g<<<dim3(128 / 32, 2048 / 32, NH), dim3(32, 8)>>>(
        qkv + 2 * DMODEL, vt, 2048, 128, 3 * DMODEL,
        /*izs=*/HD, /*ozs=*/(long long)HD * 2 * SEQ);

    // ---- fused flash attention (double-buffered K/V) ----
    flash_attn<<<dim3(16, NH), 256, FLASH_DYN_SMEM>>>(q2, k2, vt, ctx);

    // ---- ctx split ----
    split_tiles_g<<<dim3((2048 * 512 + 255) / 256, 1), 256>>>(
        ctx, c2, 2048, 4096, 4096, 0, 0);

    // ---- out = ctx @ Wo ----
    gemm_mma<<<dim3(8, 32, 1), 256, GEMM_DYN_SMEM>>>(
        c2, w2, out, 64, 4096, 0, 0, 0, 1.0f);
}

// round 14
// speedup vs baseline: 3.9509x; 1.0396x over previous
#include <cuda_runtime.h>
#include <cuda_bf16.h>
#include <math.h>
#include <stdint.h>

#define SEQ 2048
#define DMODEL 4096
#define NH 32
#define HD 128

// ===========================================================================
// PTX helpers (sm_103-safe subset)
// ===========================================================================
__device__ __forceinline__ uint32_t smem_u32(const void* p) {
    uint32_t a;
    asm("{ .reg .u64 t; cvta.to.shared.u64 t, %1; cvt.u32.u64 %0, t; }" : "=r"(a) : "l"(p));
    return a;
}
#define MBARRIER_INIT(addr, cnt) \
    asm volatile("mbarrier.init.shared.b64 [%0], %1;" :: "r"((uint32_t)(addr)), "r"((uint32_t)(cnt)) : "memory")
#define MBARRIER_EXPECT_TX(addr, bytes) \
    asm volatile("mbarrier.arrive.expect_tx.shared.b64 _, [%0], %1;" :: "r"((uint32_t)(addr)), "r"((uint32_t)(bytes)) : "memory")
#define MBARRIER_ARRIVE(addr) \
    asm volatile("mbarrier.arrive.shared.b64 _, [%0];" :: "r"((uint32_t)(addr)) : "memory")

#define MBARRIER_WAIT_PARITY(mbar_smem_addr, phase_parity) do { \
    uint32_t _mbar = (uint32_t)(mbar_smem_addr); \
    uint32_t _parity = (uint32_t)(phase_parity); \
    uint32_t _done; \
    asm volatile("{\n\t.reg .pred p;\n\t" \
        "mbarrier.try_wait.parity.acquire.cta.shared::cta.b64 p, [%1], %2;\n\t" \
        "selp.b32 %0, 1, 0, p;\n\t}" : "=r"(_done) : "r"(_mbar), "r"(_parity) : "memory"); \
    if (!_done) { \
        asm volatile("{\n\t.reg .pred P1;\n\t" \
            "WAIT_LOOP_%=:\n\t" \
            "mbarrier.try_wait.parity.acquire.cta.shared::cta.b64 P1, [%0], %1, 0x989680;\n\t" \
            "@P1 bra.uni WAIT_DONE_%=;\n\t" \
            "bra.uni WAIT_LOOP_%=;\n\t" \
            "WAIT_DONE_%=:\n\t}" :: "r"(_mbar), "r"(_parity) : "memory"); \
    } \
} while(0)

#define MBARRIER_WAIT_PARITY_RELAXED(mbar_smem_addr, phase_parity) do { \
    uint32_t _mbar = (uint32_t)(mbar_smem_addr); \
    uint32_t _parity = (uint32_t)(phase_parity); \
    uint32_t _done; \
    asm volatile("{\n\t.reg .pred p;\n\t" \
        "mbarrier.try_wait.parity.relaxed.cta.shared::cta.b64 p, [%1], %2, 0x989680;\n\t" \
        "selp.b32 %0, 1, 0, p;\n\t}" : "=r"(_done) : "r"(_mbar), "r"(_parity) : "memory"); \
    if (!_done) { \
        asm volatile("{\n\t.reg .pred P1;\n\t" \
            "WAIT_LOOP_%=:\n\t" \
            "mbarrier.try_wait.parity.relaxed.cta.shared::cta.b64 P1, [%0], %1, 0x989680;\n\t" \
            "@P1 bra.uni WAIT_DONE_%=;\n\t" \
            "bra.uni WAIT_LOOP_%=;\n\t" \
            "WAIT_DONE_%=:\n\t}" :: "r"(_mbar), "r"(_parity) : "memory"); \
    } \
} while(0)

__device__ __forceinline__ void bulk_g2s(uint32_t dst, const void* src,
                                         uint32_t bytes, uint32_t mbar) {
    asm volatile(
        "cp.async.bulk.shared::cluster.global.mbarrier::complete_tx::bytes [%0], [%1], %2, [%3];"
        :: "r"(dst), "l"(src), "r"(bytes), "r"(mbar) : "memory");
}

__device__ __forceinline__ void ldsm_x4(uint32_t addr, uint32_t& r0, uint32_t& r1,
                                        uint32_t& r2, uint32_t& r3) {
    asm volatile("ldmatrix.sync.aligned.m8n8.x4.shared.b16 {%0,%1,%2,%3}, [%4];"
        : "=r"(r0), "=r"(r1), "=r"(r2), "=r"(r3) : "r"(addr));
}

__device__ __forceinline__ void mma_bf16(float* c, uint32_t a0, uint32_t a1,
                                         uint32_t a2, uint32_t a3,
                                         uint32_t b0, uint32_t b1) {
    asm volatile(
        "mma.sync.aligned.m16n8k16.row.col.f32.bf16.bf16.f32 "
        "{%0,%1,%2,%3}, {%4,%5,%6,%7}, {%8,%9}, {%0,%1,%2,%3};"
        : "+f"(c[0]), "+f"(c[1]), "+f"(c[2]), "+f"(c[3])
        : "r"(a0), "r"(a1), "r"(a2), "r"(a3), "r"(b0), "r"(b1));
}

__device__ __forceinline__ float ex2f(float x) {
    float r;
    asm("ex2.approx.f32 %0, %1;" : "=f"(r) : "f"(x));
    return r;
}

// ===========================================================================
// Scratch (static device globals; no allocations anywhere)
// ===========================================================================
__device__ float g_qkv[(size_t)SEQ * 3 * DMODEL];
__device__ float g_ctx[(size_t)SEQ * DMODEL];
__device__ __align__(128) __nv_bfloat16 g_x2[(size_t)SEQ * 2 * DMODEL];
__device__ __align__(128) __nv_bfloat16 g_w1[(size_t)3 * DMODEL * 2 * DMODEL];
__device__ __align__(128) __nv_bfloat16 g_w2[(size_t)DMODEL * 2 * DMODEL];
__device__ __align__(128) __nv_bfloat16 g_q2[(size_t)NH * SEQ * 2 * HD];
__device__ __align__(128) __nv_bfloat16 g_k2[(size_t)NH * SEQ * 2 * HD];
__device__ __align__(128) __nv_bfloat16 g_vt[(size_t)NH * HD * 2 * SEQ];
__device__ __align__(128) __nv_bfloat16 g_c2[(size_t)SEQ * 2 * DMODEL];
__device__ float g_cos[SEQ * (HD / 2)];
__device__ float g_sin[SEQ * (HD / 2)];

// ===========================================================================
// Tiled/swizzled gmem layout: 128x64-bf16 tiles (16KB, SW128-swizzled)
// ===========================================================================
__device__ __forceinline__ size_t granule_off(int r, int k8, int ktiles) {
    int kt = k8 >> 3;
    uint32_t b = (uint32_t)((r & 127) * 128)
               + (((uint32_t)(k8 & 7) << 4) ^ ((uint32_t)(r & 7) << 4));
    return ((size_t)((r >> 7) * ktiles + kt) << 14) + b;
}

__device__ __forceinline__ void split8(const float* v, uint4& hi, uint4& lo) {
    uint32_t hw[4], lw[4];
    #pragma unroll
    for (int j = 0; j < 4; j++) {
        __nv_bfloat16 h0 = __float2bfloat16(v[2 * j]);
        __nv_bfloat16 h1 = __float2bfloat16(v[2 * j + 1]);
        __nv_bfloat16 l0 = __float2bfloat16(v[2 * j]     - __bfloat162float(h0));
        __nv_bfloat16 l1 = __float2bfloat16(v[2 * j + 1] - __bfloat162float(h1));
        hw[j] = (uint32_t)__bfloat16_as_ushort(h0) | ((uint32_t)__bfloat16_as_ushort(h1) << 16);
        lw[j] = (uint32_t)__bfloat16_as_ushort(l0) | ((uint32_t)__bfloat16_as_ushort(l1) << 16);
    }
    hi = make_uint4(hw[0], hw[1], hw[2], hw[3]);
    lo = make_uint4(lw[0], lw[1], lw[2], lw[3]);
}

__global__ __launch_bounds__(256)
void split_tiles_g(const float* __restrict__ in, __nv_bfloat16* __restrict__ out,
                   int R, int K, int ldin, long long izs, long long ozs)
{
    int z = blockIdx.y;
    long long idx = (long long)blockIdx.x * 256 + threadIdx.x;
    int kg = K / 8;
    long long tot = (long long)R * kg;
    if (idx >= tot) return;
    int r  = (int)(idx / kg);
    int k8 = (int)(idx - (long long)r * kg);
    const float* p = in + (long long)z * izs + (long long)r * ldin + k8 * 8;
    float v[8];
    float4 a = *(const float4*)p, b = *(const float4*)(p + 4);
    v[0]=a.x; v[1]=a.y; v[2]=a.z; v[3]=a.w; v[4]=b.x; v[5]=b.y; v[6]=b.z; v[7]=b.w;
    uint4 hi, lo; split8(v, hi, lo);
    char* o = (char*)(out + (long long)z * ozs);
    int ktiles = 2 * (K / 64);
    *(uint4*)(o + granule_off(r, k8, ktiles))          = hi;
    *(uint4*)(o + granule_off(r, k8 + K / 8, ktiles))  = lo;
}

__global__ __launch_bounds__(256)
void transpose_split_g(const float* __restrict__ in, __nv_bfloat16* __restrict__ out,
                       int K, int N, int ldin, long long izs, long long ozs)
{
    __shared__ float t[32][33];
    int z = blockIdx.z;
    const float* inz = in + (long long)z * izs;
    char* outz = (char*)(out + (long long)z * ozs);
    int n0 = blockIdx.x * 32, k0 = blockIdx.y * 32;
    int x = threadIdx.x, y = threadIdx.y;   // 32 x 8
    #pragma unroll
    for (int r = 0; r < 32; r += 8)
        t[y + r][x] = inz[(long long)(k0 + y + r) * ldin + n0 + x];
    __syncthreads();
    int tt = y * 32 + x;
    if (tt < 128) {
        int nn = tt >> 2, g = tt & 3;
        float v[8];
        #pragma unroll
        for (int j = 0; j < 8; j++) v[j] = t[g * 8 + j][nn];
        uint4 hi, lo; split8(v, hi, lo);
        int ktiles = 2 * (K / 64);
        int n = n0 + nn, k8 = (k0 >> 3) + g;
        *(uint4*)(outz + granule_off(n, k8, ktiles))         = hi;
        *(uint4*)(outz + granule_off(n, k8 + K / 8, ktiles)) = lo;
    }
}

// ===========================================================================
// mma.sync bf16 GEMM (3-term chunks over 2-term storage).
// BM=128, BN=128, BK=64; 128 threads (4 warps, 2x2, warp tile 64x64);
// 3-stage 32KB pipeline; 2 CTAs/SM.
// ===========================================================================
#define GST 3
#define STAGE_BYTES 32768
#define GEMM_DYN_SMEM (GST * STAGE_BYTES + 1024)

__global__ __launch_bounds__(128, 2)
void gemm_mma(const __nv_bfloat16* __restrict__ A, const __nv_bfloat16* __restrict__ B,
              float* __restrict__ C, int nk0, int ldc,
              long long Az, long long Bz, long long Cz, float alpha)
{
    extern __shared__ char dyn[];
    __shared__ __align__(8) unsigned long long s_mbar[2 * GST];

    const int tid  = threadIdx.x;
    const int wid  = tid >> 5;
    const int lane = tid & 31;
    const int wm = wid >> 1, wn = wid & 1;
    const int mt = blockIdx.x, ntb = blockIdx.y, z = blockIdx.z;
    const int nk = 3 * nk0;

    uint32_t stages = (smem_u32(dyn) + 1023u) & ~1023u;
    uint32_t mb = smem_u32(s_mbar);

    if (tid == 0) {
        #pragma unroll
        for (int i = 0; i < GST; i++)  MBARRIER_INIT(mb + i * 8, 1);
        #pragma unroll
        for (int i = GST; i < 2 * GST; i++) MBARRIER_INIT(mb + i * 8, 4);
    }
    __syncthreads();

    const char* Ab = (const char*)A + (size_t)z * Az * 2 + (((size_t)mt * (2 * nk0)) << 14);
    const char* Bb = (const char*)B + (size_t)z * Bz * 2 + (((size_t)ntb * (2 * nk0)) << 14);

    if (tid == 0) {
        for (int c = 0; c < GST - 1 && c < nk; c++) {
            int t = c / nk0, k = c % nk0;
            size_t ao = ((size_t)((t == 1 ? nk0 : 0) + k)) << 14;
            size_t bo = ((size_t)((t == 2 ? nk0 : 0) + k)) << 14;
            uint32_t st = stages + c * STAGE_BYTES;
            MBARRIER_EXPECT_TX(mb + c * 8, STAGE_BYTES);
            bulk_g2s(st,         Ab + ao, 16384, mb + c * 8);
            bulk_g2s(st + 16384, Bb + bo, 16384, mb + c * 8);
        }
    }

    const int r_a = wm * 64 + (lane & 15);
    const uint32_t a_rowoff = (uint32_t)r_a * 128;
    const uint32_t a_sw = (uint32_t)(r_a & 7) << 4;
    const uint32_t cbA  = (uint32_t)(lane >> 4) * 16;

    const int r_b = wn * 64 + (lane & 7) + ((lane >> 4) & 1) * 8;
    const uint32_t b_rowoff = 16384u + (uint32_t)r_b * 128;
    const uint32_t b_sw = (uint32_t)(r_b & 7) << 4;
    const uint32_t cbB  = (uint32_t)((lane >> 3) & 1) * 16;

    float acc[4][8][4];
    #pragma unroll
    for (int i = 0; i < 4; i++)
        #pragma unroll
        for (int j = 0; j < 8; j++)
            #pragma unroll
            for (int q = 0; q < 4; q++) acc[i][j][q] = 0.f;

    for (int c = 0; c < nk; c++) {
        if (tid == 0) {
            int jc = c + GST - 1;
            if (jc < nk) {
                int t = jc / nk0, k = jc % nk0;
                size_t ao = ((size_t)((t == 1 ? nk0 : 0) + k)) << 14;
                size_t bo = ((size_t)((t == 2 ? nk0 : 0) + k)) << 14;
                int s2 = jc % GST;
                if (jc >= GST)
                    MBARRIER_WAIT_PARITY_RELAXED(mb + (GST + s2) * 8, ((jc / GST) - 1) & 1);
                uint32_t st = stages + s2 * STAGE_BYTES;
                MBARRIER_EXPECT_TX(mb + s2 * 8, STAGE_BYTES);
                bulk_g2s(st,         Ab + ao, 16384, mb + s2 * 8);
                bulk_g2s(st + 16384, Bb + bo, 16384, mb + s2 * 8);
            }
        }

        int s = c % GST;
        MBARRIER_WAIT_PARITY(mb + s * 8, (c / GST) & 1);
        uint32_t st = stages + s * STAGE_BYTES;
        uint32_t abase = st + a_rowoff;
        uint32_t bbase = st + b_rowoff;

        #pragma unroll
        for (int kk = 0; kk < 4; kk++) {
            uint32_t a[4][4];
            uint32_t acol = a_sw ^ (cbA + kk * 32);
            #pragma unroll
            for (int mi = 0; mi < 4; mi++)
                ldsm_x4(abase + mi * 2048 + acol, a[mi][0], a[mi][1], a[mi][2], a[mi][3]);

            uint32_t b[8][2];
            uint32_t bcol = b_sw ^ (cbB + kk * 32);
            #pragma unroll
            for (int u = 0; u < 4; u++) {
                uint32_t r0, r1, r2, r3;
                ldsm_x4(bbase + u * 2048 + bcol, r0, r1, r2, r3);
                b[2 * u][0] = r0; b[2 * u][1] = r1;
                b[2 * u + 1][0] = r2; b[2 * u + 1][1] = r3;
            }

            #pragma unroll
            for (int mi = 0; mi < 4; mi++)
                #pragma unroll
                for (int nt = 0; nt < 8; nt++)
                    mma_bf16(acc[mi][nt], a[mi][0], a[mi][1], a[mi][2], a[mi][3],
                             b[nt][0], b[nt][1]);
        }

        if (lane == 0) MBARRIER_ARRIVE(mb + (GST + s) * 8);
    }

    float* Cb = C + (size_t)z * Cz;
    const int row0 = mt * 128 + wm * 64;
    const int col0 = ntb * 128 + wn * 64;
    #pragma unroll
    for (int mi = 0; mi < 4; mi++) {
        int r = row0 + mi * 16 + (lane >> 2);
        #pragma unroll
        for (int nt = 0; nt < 8; nt++) {
            int cc = col0 + nt * 8 + (lane & 3) * 2;
            float2 v0 = { acc[mi][nt][0] * alpha, acc[mi][nt][1] * alpha };
            float2 v1 = { acc[mi][nt][2] * alpha, acc[mi][nt][3] * alpha };
            *(float2*)(Cb + (size_t)r * ldc + cc)       = v0;
            *(float2*)(Cb + (size_t)(r + 8) * ldc + cc) = v1;
        }
    }
}

// ===========================================================================
// RoPE table + fused rope->split. Q gets 1/sqrt(HD) folded in.
// ===========================================================================
__global__ void build_rope_table()
{
    int idx = blockIdx.x * blockDim.x + threadIdx.x;
    if (idx >= SEQ * (HD / 2)) return;
    int i = idx % (HD / 2);
    int s = idx / (HD / 2);
    double freq_d = pow(10000.0, -(double)(2 * i) / (double)HD);
    float freq  = (float)freq_d;
    float angle = (float)s * freq;
    g_cos[idx] = (float)cos((double)angle);
    g_sin[idx] = (float)sin((double)angle);
}

__global__ __launch_bounds__(256)
void rope_split(const float* __restrict__ qkv,
                __nv_bfloat16* __restrict__ q2, __nv_bfloat16* __restrict__ k2)
{
    const float SCALE = 0.08838834764831845f;
    int idx = blockIdx.x * 256 + threadIdx.x;        // (s, h, j)
    if (idx >= SEQ * NH * 16) return;
    int j = idx & 15;
    int h = (idx >> 4) & 31;
    int s = idx >> 9;

    const float* qp = qkv + (long long)s * (3 * DMODEL) + h * HD + j * 8;
    float q[8], k[8];
    {
        float4 a = *(const float4*)qp, b = *(const float4*)(qp + 4);
        q[0]=a.x; q[1]=a.y; q[2]=a.z; q[3]=a.w; q[4]=b.x; q[5]=b.y; q[6]=b.z; q[7]=b.w;
        float4 c = *(const float4*)(qp + DMODEL), d = *(const float4*)(qp + DMODEL + 4);
        k[0]=c.x; k[1]=c.y; k[2]=c.z; k[3]=c.w; k[4]=d.x; k[5]=d.y; k[6]=d.z; k[7]=d.w;
    }
    #pragma unroll
    for (int p = 0; p < 4; p++) {
        int i = j * 4 + p;
        float c  = g_cos[s * 64 + i];
        float sn = g_sin[s * 64 + i];
        float q0 = q[2*p], q1 = q[2*p+1];
        q[2*p]   = (q0 * c - q1 * sn) * SCALE;
        q[2*p+1] = (q0 * sn + q1 * c) * SCALE;
        float k0 = k[2*p], k1 = k[2*p+1];
        k[2*p]   = k0 * c - k1 * sn;
        k[2*p+1] = k0 * sn + k1 * c;
    }
    uint4 qhi, qlo, khi, klo;
    split8(q, qhi, qlo);
    split8(k, khi, klo);
    char* qo = (char*)(q2 + (long long)h * SEQ * 2 * HD);
    char* ko = (char*)(k2 + (long long)h * SEQ * 2 * HD);
    *(uint4*)(qo + granule_off(s, j, 4))      = qhi;
    *(uint4*)(qo + granule_off(s, j + 16, 4)) = qlo;
    *(uint4*)(ko + granule_off(s, j, 4))      = khi;
    *(uint4*)(ko + granule_off(s, j + 16, 4)) = klo;
}

// ===========================================================================
// Flash attention v3: one CTA = (64 Q rows, head), 128 threads (4 warps,
// warp owns 16 rows). BN=64 K blocks, single-buffered K/V, 2 CTAs/SM —
// cross-CTA overlap hides load latency. S, softmax, P-resplit, O in regs.
// smem: Q 32K [hi_d0|hi_d1|lo_d0|lo_d1] | K 32K same | V 32K [hi|lo]
// ===========================================================================
#define FLASH_DYN_SMEM (3 * 32768 + 1024)

__global__ __launch_bounds__(128, 2)
void flash_attn(const __nv_bfloat16* __restrict__ q2,
                const __nv_bfloat16* __restrict__ k2,
                const __nv_bfloat16* __restrict__ vt,
                float* __restrict__ ctx)
{
    extern __shared__ char dyn[];
    __shared__ __align__(8) unsigned long long s_mbar[5];
    // 0: qfull | 1: kfull | 2: kempty | 3: vfull | 4: vempty

    const int tid = threadIdx.x, wid = tid >> 5, lane = tid & 31;
    const int qb = blockIdx.x, h = blockIdx.y;
    const float L2E = 1.44269504f;

    uint32_t base = (smem_u32(dyn) + 1023u) & ~1023u;
    uint32_t Qs = base, Ks = base + 32768, Vs = base + 65536;
    uint32_t mb = smem_u32(s_mbar);

    if (tid == 0) {
        MBARRIER_INIT(mb + 0, 1);
        MBARRIER_INIT(mb + 8, 1);
        MBARRIER_INIT(mb + 16, 4);
        MBARRIER_INIT(mb + 24, 1);
        MBARRIER_INIT(mb + 32, 4);
    }
    __syncthreads();

    const char* Qg = (const char*)q2 + (size_t)h * SEQ * 2 * HD * 2
                   + (((size_t)(qb >> 1) * 4) << 14) + (size_t)(qb & 1) * 8192;
    const char* Kg = (const char*)k2 + (size_t)h * SEQ * 2 * HD * 2;
    const char* Vg = (const char*)vt + (size_t)h * HD * 2 * SEQ * 2;

    // K block j (64 rows): 4 x 8KB chunks [hi_d0, hi_d1, lo_d0, lo_d1]
    auto load_k = [&](int j) {
        size_t tr = ((size_t)(j >> 1) * 4) << 14;
        size_t half = (size_t)(j & 1) * 8192;
        MBARRIER_EXPECT_TX(mb + 8, 32768);
        #pragma unroll
        for (int kt = 0; kt < 4; kt++)
            bulk_g2s(Ks + kt * 8192, Kg + tr + ((size_t)kt << 14) + half, 8192, mb + 8);
    };
    // V block j (64 s-cols): hi tile j, lo tile 32+j
    auto load_v = [&](int j) {
        MBARRIER_EXPECT_TX(mb + 24, 32768);
        bulk_g2s(Vs,         Vg + ((size_t)j << 14),        16384, mb + 24);
        bulk_g2s(Vs + 16384, Vg + ((size_t)(32 + j) << 14), 16384, mb + 24);
    };

    if (tid == 0) {
        MBARRIER_EXPECT_TX(mb + 0, 32768);
        #pragma unroll
        for (int kt = 0; kt < 4; kt++)
            bulk_g2s(Qs + kt * 8192, Qg + ((size_t)kt << 14), 8192, mb + 0);
        load_k(0);
        load_v(0);
    }

    // A (Q/P) lane addressing: warp owns rows wid*16..+15 (local 0..63)
    const int r_a = wid * 16 + (lane & 15);
    const uint32_t a_row = (uint32_t)r_a * 128;
    const uint32_t a_sw  = ((uint32_t)(r_a & 7)) << 4;
    const uint32_t a_kh  = ((uint32_t)(lane >> 4)) * 16;
    // B (K/V^T) lane addressing
    const int r_b = (lane & 7) + ((lane >> 4) & 1) * 8;
    const uint32_t b_sw = ((uint32_t)(r_b & 7)) << 4;
    const uint32_t b_kh = ((uint32_t)((lane >> 3) & 1)) * 16;

    float oacc[16][4];
    #pragma unroll
    for (int i = 0; i < 16; i++)
        #pragma unroll
        for (int q = 0; q < 4; q++) oacc[i][q] = 0.f;
    float m0 = -1e30f, m1 = -1e30f, l0 = 0.f, l1 = 0.f;

    MBARRIER_WAIT_PARITY(mb + 0, 0);   // Q resident

    for (int j = 0; j < 32; j++) {
        const int ph = j & 1;
        float sacc[8][4];
        #pragma unroll
        for (int i = 0; i < 8; i++)
            #pragma unroll
            for (int q = 0; q < 4; q++) sacc[i][q] = 0.f;

        MBARRIER_WAIT_PARITY(mb + 8, ph);   // K(j) ready

        // ---- S(64x64) = Q @ K^T (3 terms) ----
        #pragma unroll
        for (int t = 0; t < 3; t++) {
            uint32_t qtb = Qs + (t == 1 ? 16384 : 0);
            uint32_t ktb = Ks + (t == 2 ? 16384 : 0);
            #pragma unroll
            for (int kk = 0; kk < 8; kk++) {
                uint32_t a0, a1, a2, a3;
                ldsm_x4(qtb + (kk >> 2) * 8192 + a_row + (a_sw ^ (a_kh + (kk & 3) * 32)),
                        a0, a1, a2, a3);
                uint32_t kbb = ktb + (kk >> 2) * 8192;
                uint32_t kcol = b_sw ^ (b_kh + (kk & 3) * 32);
                #pragma unroll
                for (int u = 0; u < 4; u++) {
                    uint32_t b0, b1, b2, b3;
                    ldsm_x4(kbb + (uint32_t)(r_b + u * 16) * 128 + kcol, b0, b1, b2, b3);
                    mma_bf16(sacc[2 * u],     a0, a1, a2, a3, b0, b1);
                    mma_bf16(sacc[2 * u + 1], a0, a1, a2, a3, b2, b3);
                }
            }
        }

        // release K(j); producer prefetches K(j+1) (overlaps softmax + PV)
        if (lane == 0) MBARRIER_ARRIVE(mb + 16);
        if (tid == 0 && j + 1 < 32) {
            MBARRIER_WAIT_PARITY_RELAXED(mb + 16, ph);
            load_k(j + 1);
        }

        // ---- online softmax ----
        float rmax0 = -1e30f, rmax1 = -1e30f;
        #pragma unroll
        for (int i = 0; i < 8; i++) {
            rmax0 = fmaxf(rmax0, fmaxf(sacc[i][0], sacc[i][1]));
            rmax1 = fmaxf(rmax1, fmaxf(sacc[i][2], sacc[i][3]));
        }
        rmax0 = fmaxf(rmax0, __shfl_xor_sync(0xffffffffu, rmax0, 1));
        rmax0 = fmaxf(rmax0, __shfl_xor_sync(0xffffffffu, rmax0, 2));
        rmax1 = fmaxf(rmax1, __shfl_xor_sync(0xffffffffu, rmax1, 1));
        rmax1 = fmaxf(rmax1, __shfl_xor_sync(0xffffffffu, rmax1, 2));
        float mn0 = fmaxf(m0, rmax0), mn1 = fmaxf(m1, rmax1);
        float c0 = ex2f((m0 - mn0) * L2E), c1 = ex2f((m1 - mn1) * L2E);
        float rs0 = 0.f, rs1 = 0.f;
        #pragma unroll
        for (int i = 0; i < 8; i++) {
            float p0 = ex2f((sacc[i][0] - mn0) * L2E);
            float p1 = ex2f((sacc[i][1] - mn0) * L2E);
            float p2 = ex2f((sacc[i][2] - mn1) * L2E);
            float p3 = ex2f((sacc[i][3] - mn1) * L2E);
            sacc[i][0] = p0; sacc[i][1] = p1; sacc[i][2] = p2; sacc[i][3] = p3;
            rs0 += p0 + p1; rs1 += p2 + p3;
        }
        rs0 += __shfl_xor_sync(0xffffffffu, rs0, 1);
        rs0 += __shfl_xor_sync(0xffffffffu, rs0, 2);
        rs1 += __shfl_xor_sync(0xffffffffu, rs1, 1);
        rs1 += __shfl_xor_sync(0xffffffffu, rs1, 2);
        l0 = l0 * c0 + rs0;  l1 = l1 * c1 + rs1;
        m0 = mn0; m1 = mn1;
        #pragma unroll
        for (int i = 0; i < 16; i++) {
            oacc[i][0] *= c0; oacc[i][1] *= c0;
            oacc[i][2] *= c1; oacc[i][3] *= c1;
        }

        // ---- O += P @ V (3 terms: PhVh, PlVh, PhVl) ----
        MBARRIER_WAIT_PARITY(mb + 24, ph);   // V(j) ready
        #pragma unroll
        for (int u = 0; u < 4; u++) {        // k16 over the 64 seq cols
            uint32_t phr[4], plr[4];
            {
                float e00 = sacc[2*u][0],   e01 = sacc[2*u][1];
                float e10 = sacc[2*u][2],   e11 = sacc[2*u][3];
                float e20 = sacc[2*u+1][0], e21 = sacc[2*u+1][1];
                float e30 = sacc[2*u+1][2], e31 = sacc[2*u+1][3];
                __nv_bfloat16 h00=__float2bfloat16(e00), h01=__float2bfloat16(e01);
                __nv_bfloat16 h10=__float2bfloat16(e10), h11=__float2bfloat16(e11);
                __nv_bfloat16 h20=__float2bfloat16(e20), h21=__float2bfloat16(e21);
                __nv_bfloat16 h30=__float2bfloat16(e30), h31=__float2bfloat16(e31);
                phr[0] = (uint32_t)__bfloat16_as_ushort(h00) | ((uint32_t)__bfloat16_as_ushort(h01) << 16);
                phr[1] = (uint32_t)__bfloat16_as_ushort(h10) | ((uint32_t)__bfloat16_as_ushort(h11) << 16);
                phr[2] = (uint32_t)__bfloat16_as_ushort(h20) | ((uint32_t)__bfloat16_as_ushort(h21) << 16);
                phr[3] = (uint32_t)__bfloat16_as_ushort(h30) | ((uint32_t)__bfloat16_as_ushort(h31) << 16);
                __nv_bfloat16 q00=__float2bfloat16(e00-__bfloat162float(h00));
                __nv_bfloat16 q01=__float2bfloat16(e01-__bfloat162float(h01));
                __nv_bfloat16 q10=__float2bfloat16(e10-__bfloat162float(h10));
                __nv_bfloat16 q11=__float2bfloat16(e11-__bfloat162float(h11));
                __nv_bfloat16 q20=__float2bfloat16(e20-__bfloat162float(h20));
                __nv_bfloat16 q21=__float2bfloat16(e21-__bfloat162float(h21));
                __nv_bfloat16 q30=__float2bfloat16(e30-__bfloat162float(h30));
                __nv_bfloat16 q31=__float2bfloat16(e31-__bfloat162float(h31));
                plr[0] = (uint32_t)__bfloat16_as_ushort(q00) | ((uint32_t)__bfloat16_as_ushort(q01) << 16);
                plr[1] = (uint32_t)__bfloat16_as_ushort(q10) | ((uint32_t)__bfloat16_as_ushort(q11) << 16);
                plr[2] = (uint32_t)__bfloat16_as_ushort(q20) | ((uint32_t)__bfloat16_as_ushort(q21) << 16);
                plr[3] = (uint32_t)__bfloat16_as_ushort(q30) | ((uint32_t)__bfloat16_as_ushort(q31) << 16);
            }
            uint32_t vhb = Vs;
            uint32_t vlb = Vs + 16384;
            uint32_t vcol = b_sw ^ (b_kh + u * 32);
            #pragma unroll
            for (int v = 0; v < 8; v++) {    // n16 over d=128
                uint32_t roff = (uint32_t)(r_b + v * 16) * 128 + vcol;
                uint32_t b0, b1, b2, b3;
                ldsm_x4(vhb + roff, b0, b1, b2, b3);
                mma_bf16(oacc[2 * v],     phr[0], phr[1], phr[2], phr[3], b0, b1);
                mma_bf16(oacc[2 * v + 1], phr[0], phr[1], phr[2], phr[3], b2, b3);
                mma_bf16(oacc[2 * v],     plr[0], plr[1], plr[2], plr[3], b0, b1);
                mma_bf16(oacc[2 * v + 1], plr[0], plr[1], plr[2], plr[3], b2, b3);
                uint32_t c0r, c1r, c2r, c3r;
                ldsm_x4(vlb + roff, c0r, c1r, c2r, c3r);
                mma_bf16(oacc[2 * v],     phr[0], phr[1], phr[2], phr[3], c0r, c1r);
                mma_bf16(oacc[2 * v + 1], phr[0], phr[1], phr[2], phr[3], c2r, c3r);
            }
        }

        // release V(j); producer prefetches V(j+1) (overlaps next S)
        if (lane == 0) MBARRIER_ARRIVE(mb + 32);
        if (tid == 0 && j + 1 < 32) {
            MBARRIER_WAIT_PARITY_RELAXED(mb + 32, ph);
            load_v(j + 1);
        }
    }

    // ---- epilogue: O / l -> ctx[s, h*128 + d] fp32 ----
    float i0 = 1.0f / l0, i1 = 1.0f / l1;
    int srow = qb * 64 + wid * 16 + (lane >> 2);
    float* C0 = ctx + (size_t)srow * DMODEL + h * HD;
    #pragma unroll
    for (int nt = 0; nt < 16; nt++) {
        int cc = nt * 8 + (lane & 3) * 2;
        float2 v0 = { oacc[nt][0] * i0, oacc[nt][1] * i0 };
        float2 v1 = { oacc[nt][2] * i1, oacc[nt][3] * i1 };
        *(float2*)(C0 + cc)               = v0;
        *(float2*)(C0 + 8 * DMODEL + cc)  = v1;
    }
}

// ===========================================================================
extern "C" void kernel_launch(void* const* d_in, const int* in_sizes, int n_in,
                              void* d_out, int out_size)
{
    const float* hidden = (const float*)d_in[0];   // [2048, 4096]
    const float* wqkv   = (const float*)d_in[1];   // [4096, 12288]
    const float* wo     = (const float*)d_in[2];   // [4096, 4096]
    float* out = (float*)d_out;                    // [2048, 4096]

    float *qkv, *ctx;
    __nv_bfloat16 *x2, *w1, *w2, *q2, *k2, *vt, *c2;
    cudaGetSymbolAddress((void**)&qkv, g_qkv);
    cudaGetSymbolAddress((void**)&ctx, g_ctx);
    cudaGetSymbolAddress((void**)&x2, g_x2);
    cudaGetSymbolAddress((void**)&w1, g_w1);
    cudaGetSymbolAddress((void**)&w2, g_w2);
    cudaGetSymbolAddress((void**)&q2, g_q2);
    cudaGetSymbolAddress((void**)&k2, g_k2);
    cudaGetSymbolAddress((void**)&vt, g_vt);
    cudaGetSymbolAddress((void**)&c2, g_c2);

    cudaFuncSetAttribute(gemm_mma, cudaFuncAttributeMaxDynamicSharedMemorySize, GEMM_DYN_SMEM);
    cudaFuncSetAttribute(flash_attn, cudaFuncAttributeMaxDynamicSharedMemorySize, FLASH_DYN_SMEM);

    // ---- operand conversion ----
    split_tiles_g<<<dim3((2048 * 512 + 255) / 256, 1), 256>>>(
        hidden, x2, 2048, 4096, 4096, 0, 0);
    transpose_split_g<<<dim3(12288 / 32, 4096 / 32, 1), dim3(32, 8)>>>(
        wqkv, w1, 4096, 12288, 12288, 0, 0);
    transpose_split_g<<<dim3(4096 / 32, 4096 / 32, 1), dim3(32, 8)>>>(
        wo, w2, 4096, 4096, 4096, 0, 0);

    // ---- QKV GEMM: [2048, 12288] (BM=128 tiles, 2 CTAs/SM) ----
    gemm_mma<<<dim3(16, 96, 1), 128, GEMM_DYN_SMEM>>>(
        x2, w1, qkv, 64, 12288, 0, 0, 0, 1.0f);

    // ---- RoPE + Q/K split (scale folded into Q) ----
    build_rope_table<<<(SEQ * (HD / 2) + 255) / 256, 256>>>();
    rope_split<<<(SEQ * NH * 16 + 255) / 256, 256>>>(qkv, q2, k2);

    // ---- V^T split per head ----
    transpose_split_g<<<dim3(128 / 32, 2048 / 32, NH), dim3(32, 8)>>>(
        qkv + 2 * DMODEL, vt, 2048, 128, 3 * DMODEL,
        /*izs=*/HD, /*ozs=*/(long long)HD * 2 * SEQ);

    // ---- fused flash attention (64-row CTAs, 2/SM) ----
    flash_attn<<<dim3(32, NH), 128, FLASH_DYN_SMEM>>>(q2, k2, vt, ctx);

    // ---- ctx split ----
    split_tiles_g<<<dim3((2048 * 512 + 255) / 256, 1), 256>>>(
        ctx, c2, 2048, 4096, 4096, 0, 0);

    // ---- out = ctx @ Wo ----
    gemm_mma<<<dim3(16, 32, 1), 128, GEMM_DYN_SMEM>>>(
        c2, w2, out, 64, 4096, 0, 0, 0, 1.0f);
}